// round 11
// baseline (speedup 1.0000x reference)
#include <cuda_runtime.h>
#include <cuda_fp16.h>
#include <cuda_bf16.h>
#include <stdint.h>

#define NN 50000
#define EE 800000
#define DD 64
#define NB 196            // scan chunks of 256
#define NBLK 296          // 148 SMs x 2 — all co-resident
#define NTHR 256
#define NTILES 391        // ceil(NN/128) gemm tiles

// ---------------- device scratch (static, no allocation) ----------------
__device__ int   g_flag;
__device__ int   g_cnt[NN];
__device__ int   g_rowptr[NN + 1];
__device__ int   g_fill[NN];
__device__ int   g_bsum[NB];
__device__ unsigned g_barcnt = 0;
__device__ unsigned g_bargen = 0;
__device__ unsigned short g_srcs16[EE];
__device__ unsigned short g_dst16[EE];
__device__ float g_pe[EE];                                  // per-edge exp
__device__ float g_z[NN];                                   // per-dst sum
__device__ __align__(16) unsigned short g_xh[NN * DD];      // x hi (bf16)
__device__ __align__(16) unsigned short g_xl[NN * DD];      // x lo (bf16)
__device__ __align__(16) unsigned short g_Wh[8 * DD * DD];  // W^T hi
__device__ __align__(16) unsigned short g_Wl[8 * DD * DD];  // W^T lo
__device__ __align__(16) __half g_hh[NN * DD];              // h (fp16)
__device__ float g_ssrc[NN];
__device__ float g_sdst[NN];

__device__ __forceinline__ void split_bf16(float v, unsigned short& hi, unsigned short& lo) {
    __nv_bfloat16 h = __float2bfloat16(v);
    float r = v - __bfloat162float(h);
    __nv_bfloat16 l = __float2bfloat16(r);
    hi = *reinterpret_cast<unsigned short*>(&h);
    lo = *reinterpret_cast<unsigned short*>(&l);
}

// software grid barrier (all NBLK blocks co-resident by construction)
__device__ __forceinline__ void gsync() {
    __syncthreads();
    if (threadIdx.x == 0) {
        __threadfence();
        unsigned gen = *((volatile unsigned*)&g_bargen);
        if (atomicAdd(&g_barcnt, 1) == NBLK - 1) {
            g_barcnt = 0;
            __threadfence();
            atomicAdd(&g_bargen, 1);
        } else {
            while (*((volatile unsigned*)&g_bargen) == gen) __nanosleep(64);
        }
        __threadfence();
    }
    __syncthreads();
}

__global__ void __launch_bounds__(NTHR, 2) k_fused(
        const int* __restrict__ raw,
        const float* __restrict__ feat,
        const float* __restrict__ W1, const float* __restrict__ W2,
        const float* __restrict__ a_s1, const float* __restrict__ a_d1,
        const float* __restrict__ a_s2, const float* __restrict__ a_d2,
        float* __restrict__ out, int E) {
    extern __shared__ __align__(16) char smem[];
    unsigned short (*Ah)[72] = (unsigned short(*)[72])(smem);          // 18432
    unsigned short (*Al)[72] = (unsigned short(*)[72])(smem + 18432);  // 18432
    unsigned short (*Bh)[72] = (unsigned short(*)[72])(smem + 36864);  //  9216
    unsigned short (*Bl)[72] = (unsigned short(*)[72])(smem + 46080);  //  9216
    int* sh = (int*)(smem + 55296);                                    //  1024

    const int tid = threadIdx.x;
    const int bid = blockIdx.x;
    const int gt  = bid * NTHR + tid;
    const int gsz = NBLK * NTHR;
    const int lane = tid & 31;

    // ---------- phase 0: init (cvt feat, cvt W, zero cnt, detect dtype) --
    for (int i = gt; i < NN * DD; i += gsz) split_bf16(feat[i], g_xh[i], g_xl[i]);
    for (int i = gt; i < 8 * DD * DD; i += gsz) {
        int g = i >> 12, idx = i & 4095;
        int k = idx >> 6, c = idx & 63;
        const float* W = (g < 4) ? W1 : W2;
        split_bf16(W[(g & 3) * DD * DD + k * DD + c],
                   g_Wh[g * DD * DD + c * DD + k], g_Wl[g * DD * DD + c * DD + k]);
    }
    for (int i = gt; i < NN; i += gsz) g_cnt[i] = 0;
    if (bid == 0) {
        int bad = 0;
        for (int j = tid; j < 4096; j += NTHR)
            if (raw[2 * j + 1] != 0) bad = 1;
        int anybad = __syncthreads_or(bad);
        if (tid == 0) g_flag = anybad ? 0 : 1;   // 1 = int64 layout
    }
    gsync();

    // ---------- phase 1: histogram of dst -------------------------------
    const int nq = (E + 3) / 4;
    if (g_flag) {
        const long long* p = (const long long*)raw + E;
        for (int q = gt; q < nq; q += gsz) {
            int base = q * 4;
#pragma unroll
            for (int u = 0; u < 4; u++) {
                int j = base + u;
                if (j < E) atomicAdd(&g_cnt[(int)p[j]], 1);
            }
        }
    } else {
        const int* p = (const int*)raw + E;
        for (int q = gt; q < nq; q += gsz) {
            int base = q * 4;
#pragma unroll
            for (int u = 0; u < 4; u++) {
                int j = base + u;
                if (j < E) atomicAdd(&g_cnt[p[j]], 1);
            }
        }
    }
    gsync();

    // ---------- phase 2: scan A (block-local) ----------------------------
    if (bid < NB) {
        int i = bid * 256 + tid;
        int v = (i < NN) ? g_cnt[i] : 0;
        sh[tid] = v;
        __syncthreads();
#pragma unroll
        for (int off = 1; off < 256; off <<= 1) {
            int u = (tid >= off) ? sh[tid - off] : 0;
            __syncthreads();
            sh[tid] += u;
            __syncthreads();
        }
        if (i < NN) g_rowptr[i] = sh[tid] - v;
        if (tid == 255) g_bsum[bid] = sh[255];
    }
    gsync();

    // ---------- phase 3: scan C (lookback + apply) ------------------------
    if (bid < NB) {
        int partial = 0;
        for (int j = tid; j < bid; j += 256) partial += g_bsum[j];
#pragma unroll
        for (int o = 16; o; o >>= 1) partial += __shfl_xor_sync(0xffffffffu, partial, o);
        if ((tid & 31) == 0) sh[tid >> 5] = partial;
        __syncthreads();
        if (tid == 0) {
            int s = 0;
#pragma unroll
            for (int i = 0; i < 8; i++) s += sh[i];
            sh[8] = s;
        }
        __syncthreads();
        int off = sh[8];
        int i = bid * 256 + tid;
        if (i < NN) {
            int r = g_rowptr[i] + off;
            g_rowptr[i] = r;
            g_fill[i] = r;
        }
        if (i == 0) g_rowptr[NN] = E;
    }
    gsync();

    // ---------- phase 4: scatter into CSR (src + dst) ---------------------
    if (g_flag) {
        const long long* p = (const long long*)raw;
        for (int q = gt; q < nq; q += gsz) {
            int base = q * 4;
#pragma unroll
            for (int u = 0; u < 4; u++) {
                int j = base + u;
                if (j < E) {
                    int s = (int)p[j], d = (int)p[E + j];
                    int pos = atomicAdd(&g_fill[d], 1);
                    g_srcs16[pos] = (unsigned short)s;
                    g_dst16[pos] = (unsigned short)d;
                }
            }
        }
    } else {
        const int* p = (const int*)raw;
        for (int q = gt; q < nq; q += gsz) {
            int base = q * 4;
#pragma unroll
            for (int u = 0; u < 4; u++) {
                int j = base + u;
                if (j < E) {
                    int s = p[j], d = p[E + j];
                    int pos = atomicAdd(&g_fill[d], 1);
                    g_srcs16[pos] = (unsigned short)s;
                    g_dst16[pos] = (unsigned short)d;
                }
            }
        }
    }
    gsync();

    // ---------- conv loop: 8 x (gemm -> aggA -> aggB) ---------------------
    const int gwarp = gt >> 5;
    const int twarp = gsz >> 5;
    const int gid = lane >> 2, tig = lane & 3;

    for (int g = 0; g < 8; g++) {
        const float* as = ((g < 4) ? a_s1 : a_s2) + (g & 3) * DD;
        const float* ad = ((g < 4) ? a_d1 : a_d2) + (g & 3) * DD;
        const int is_last = (g == 7);
        const int do_elu  = ((g & 3) == 3);

        // stage W^T for this head
        for (int i = tid; i < 512; i += NTHR) {
            int c = i >> 3, q = i & 7;
            ((uint4*)&Bh[c][0])[q] = ((const uint4*)(g_Wh + g * DD * DD + c * DD))[q];
            ((uint4*)&Bl[c][0])[q] = ((const uint4*)(g_Wl + g * DD * DD + c * DD))[q];
        }
        __syncthreads();

        // ---- gemm: h = x @ W (3-term bf16 split), fused projections -----
        for (int tile = bid; tile < NTILES; tile += NBLK) {
            int rb = tile * 128;
            for (int i = tid; i < 1024; i += NTHR) {
                int r = i >> 3, q = i & 7;
                int gr = rb + r; if (gr >= NN) gr = 0;
                ((uint4*)&Ah[r][0])[q] = ((const uint4*)(g_xh + (size_t)gr * DD))[q];
                ((uint4*)&Al[r][0])[q] = ((const uint4*)(g_xl + (size_t)gr * DD))[q];
            }
            __syncthreads();

            int wid = tid >> 5;
            float acc[8][4];
#pragma unroll
            for (int nt = 0; nt < 8; nt++)
#pragma unroll
                for (int q = 0; q < 4; q++) acc[nt][q] = 0.f;

#pragma unroll
            for (int ks = 0; ks < 4; ks++) {
                int k0 = ks * 16 + 2 * tig;
                int r0 = wid * 16 + gid;
                uint32_t ahi[4], alo[4];
                ahi[0] = *(const uint32_t*)&Ah[r0][k0];
                ahi[1] = *(const uint32_t*)&Ah[r0 + 8][k0];
                ahi[2] = *(const uint32_t*)&Ah[r0][k0 + 8];
                ahi[3] = *(const uint32_t*)&Ah[r0 + 8][k0 + 8];
                alo[0] = *(const uint32_t*)&Al[r0][k0];
                alo[1] = *(const uint32_t*)&Al[r0 + 8][k0];
                alo[2] = *(const uint32_t*)&Al[r0][k0 + 8];
                alo[3] = *(const uint32_t*)&Al[r0 + 8][k0 + 8];
#pragma unroll
                for (int nt = 0; nt < 8; nt++) {
                    int n = nt * 8 + gid;
                    uint32_t bhi[2], blo[2];
                    bhi[0] = *(const uint32_t*)&Bh[n][k0];
                    bhi[1] = *(const uint32_t*)&Bh[n][k0 + 8];
                    blo[0] = *(const uint32_t*)&Bl[n][k0];
                    blo[1] = *(const uint32_t*)&Bl[n][k0 + 8];
                    asm volatile(
                        "mma.sync.aligned.m16n8k16.row.col.f32.bf16.bf16.f32 "
                        "{%0,%1,%2,%3}, {%4,%5,%6,%7}, {%8,%9}, {%0,%1,%2,%3};"
                        : "+f"(acc[nt][0]), "+f"(acc[nt][1]), "+f"(acc[nt][2]), "+f"(acc[nt][3])
                        : "r"(ahi[0]), "r"(ahi[1]), "r"(ahi[2]), "r"(ahi[3]),
                          "r"(bhi[0]), "r"(bhi[1]));
                    asm volatile(
                        "mma.sync.aligned.m16n8k16.row.col.f32.bf16.bf16.f32 "
                        "{%0,%1,%2,%3}, {%4,%5,%6,%7}, {%8,%9}, {%0,%1,%2,%3};"
                        : "+f"(acc[nt][0]), "+f"(acc[nt][1]), "+f"(acc[nt][2]), "+f"(acc[nt][3])
                        : "r"(ahi[0]), "r"(ahi[1]), "r"(ahi[2]), "r"(ahi[3]),
                          "r"(blo[0]), "r"(blo[1]));
                    asm volatile(
                        "mma.sync.aligned.m16n8k16.row.col.f32.bf16.bf16.f32 "
                        "{%0,%1,%2,%3}, {%4,%5,%6,%7}, {%8,%9}, {%0,%1,%2,%3};"
                        : "+f"(acc[nt][0]), "+f"(acc[nt][1]), "+f"(acc[nt][2]), "+f"(acc[nt][3])
                        : "r"(alo[0]), "r"(alo[1]), "r"(alo[2]), "r"(alo[3]),
                          "r"(bhi[0]), "r"(bhi[1]));
                }
            }

            // epilogue: h -> fp16, projections, zero z
            int r0 = rb + wid * 16 + gid;
            float ss0 = 0.f, sd0 = 0.f, ss1 = 0.f, sd1 = 0.f;
#pragma unroll
            for (int nt = 0; nt < 8; nt++) {
                float2 av = ((const float2*)as)[nt * 4 + tig];
                float2 dv = ((const float2*)ad)[nt * 4 + tig];
                ss0 = fmaf(acc[nt][0], av.x, fmaf(acc[nt][1], av.y, ss0));
                sd0 = fmaf(acc[nt][0], dv.x, fmaf(acc[nt][1], dv.y, sd0));
                ss1 = fmaf(acc[nt][2], av.x, fmaf(acc[nt][3], av.y, ss1));
                sd1 = fmaf(acc[nt][2], dv.x, fmaf(acc[nt][3], dv.y, sd1));
            }
#pragma unroll
            for (int o = 1; o <= 2; o <<= 1) {
                ss0 += __shfl_xor_sync(0xffffffffu, ss0, o);
                sd0 += __shfl_xor_sync(0xffffffffu, sd0, o);
                ss1 += __shfl_xor_sync(0xffffffffu, ss1, o);
                sd1 += __shfl_xor_sync(0xffffffffu, sd1, o);
            }
            bool ok0 = (r0 < NN), ok1 = (r0 + 8 < NN);
#pragma unroll
            for (int nt = 0; nt < 8; nt++) {
                int col = nt * 8 + 2 * tig;
                if (ok0)
                    *(__half2*)(g_hh + (size_t)r0 * DD + col) =
                        __floats2half2_rn(acc[nt][0], acc[nt][1]);
                if (ok1)
                    *(__half2*)(g_hh + (size_t)(r0 + 8) * DD + col) =
                        __floats2half2_rn(acc[nt][2], acc[nt][3]);
            }
            if (tig == 0) {
                if (ok0) { g_ssrc[r0] = ss0; g_sdst[r0] = sd0; g_z[r0] = 0.f; }
                if (ok1) { g_ssrc[r0 + 8] = ss1; g_sdst[r0 + 8] = sd1; g_z[r0 + 8] = 0.f; }
            }
            __syncthreads();
        }
        gsync();

        // ---- aggA: edge-parallel exp + z accumulation -------------------
#pragma unroll 2
        for (int j = gt; j < E; j += gsz) {
            int s = g_srcs16[j];
            int d = g_dst16[j];
            float e = g_ssrc[s] + g_sdst[d];
            e = (e > 0.f) ? e : 0.2f * e;
            float p = __expf(fminf(e, 60.f));
            g_pe[j] = p;
            atomicAdd(&g_z[d], p);
        }
        gsync();

        // ---- aggB: node-parallel weighted gather ------------------------
        {
            int q = lane >> 3, l8 = lane & 7;
            const uint4* h16 = (const uint4*)g_hh;
            for (int w = gwarp; w < NN; w += twarp) {
                int start = g_rowptr[w], end = g_rowptr[w + 1];
                float inv = 1.f / (g_z[w] + 1e-16f);
                float acc[8];
#pragma unroll
                for (int i = 0; i < 8; i++) acc[i] = 0.f;
#pragma unroll 4
                for (int j = start + q; j < end; j += 4) {
                    int s = g_srcs16[j];
                    float wgt = g_pe[j] * inv;
                    uint4 hv = h16[(size_t)s * 8 + l8];
                    float2 f0 = __half22float2(*reinterpret_cast<const __half2*>(&hv.x));
                    float2 f1 = __half22float2(*reinterpret_cast<const __half2*>(&hv.y));
                    float2 f2 = __half22float2(*reinterpret_cast<const __half2*>(&hv.z));
                    float2 f3 = __half22float2(*reinterpret_cast<const __half2*>(&hv.w));
                    acc[0] = fmaf(f0.x, wgt, acc[0]);
                    acc[1] = fmaf(f0.y, wgt, acc[1]);
                    acc[2] = fmaf(f1.x, wgt, acc[2]);
                    acc[3] = fmaf(f1.y, wgt, acc[3]);
                    acc[4] = fmaf(f2.x, wgt, acc[4]);
                    acc[5] = fmaf(f2.y, wgt, acc[5]);
                    acc[6] = fmaf(f3.x, wgt, acc[6]);
                    acc[7] = fmaf(f3.y, wgt, acc[7]);
                }
#pragma unroll
                for (int i = 0; i < 8; i++) {
                    acc[i] += __shfl_xor_sync(0xffffffffu, acc[i], 8);
                    acc[i] += __shfl_xor_sync(0xffffffffu, acc[i], 16);
                }
                if (q == 0) {
                    if (do_elu) {
#pragma unroll
                        for (int i = 0; i < 8; i++)
                            acc[i] = (acc[i] > 0.f) ? acc[i] : (__expf(acc[i]) - 1.f);
                    }
                    if (is_last) {
                        float4 v0 = make_float4(acc[0], acc[1], acc[2], acc[3]);
                        float4 v1 = make_float4(acc[4], acc[5], acc[6], acc[7]);
                        ((float4*)out)[(size_t)w * 16 + l8 * 2]     = v0;
                        ((float4*)out)[(size_t)w * 16 + l8 * 2 + 1] = v1;
                    } else {
                        ushort4 hh0, ll0, hh1, ll1;
                        split_bf16(acc[0], hh0.x, ll0.x);
                        split_bf16(acc[1], hh0.y, ll0.y);
                        split_bf16(acc[2], hh0.z, ll0.z);
                        split_bf16(acc[3], hh0.w, ll0.w);
                        split_bf16(acc[4], hh1.x, ll1.x);
                        split_bf16(acc[5], hh1.y, ll1.y);
                        split_bf16(acc[6], hh1.z, ll1.z);
                        split_bf16(acc[7], hh1.w, ll1.w);
                        *(ushort4*)(g_xh + (size_t)w * DD + l8 * 8)     = hh0;
                        *(ushort4*)(g_xh + (size_t)w * DD + l8 * 8 + 4) = hh1;
                        *(ushort4*)(g_xl + (size_t)w * DD + l8 * 8)     = ll0;
                        *(ushort4*)(g_xl + (size_t)w * DD + l8 * 8 + 4) = ll1;
                    }
                }
            }
        }
        gsync();
    }
}

// ---------------- launch ----------------
extern "C" void kernel_launch(void* const* d_in, const int* in_sizes, int n_in,
                              void* d_out, int out_size) {
    const float* feat  = (const float*)d_in[0];
    const int*   eidx  = (const int*)d_in[1];
    const float* W1    = (const float*)d_in[2];
    const float* a_s1  = (const float*)d_in[3];
    const float* a_d1  = (const float*)d_in[4];
    const float* W2    = (const float*)d_in[5];
    const float* a_s2  = (const float*)d_in[6];
    const float* a_d2  = (const float*)d_in[7];
    float* out = (float*)d_out;

    int E = in_sizes[1] / 2;

    static int attr_set = 0;
    if (!attr_set) {
        cudaFuncSetAttribute(k_fused, cudaFuncAttributeMaxDynamicSharedMemorySize, 56320);
        attr_set = 1;
    }

    k_fused<<<NBLK, NTHR, 56320>>>(eidx, feat, W1, W2,
                                   a_s1, a_d1, a_s2, a_d2, out, E);
}

// round 12
// speedup vs baseline: 1.5467x; 1.5467x over previous
#include <cuda_runtime.h>
#include <cuda_fp16.h>
#include <cuda_bf16.h>
#include <stdint.h>

#define NN 50000
#define EE 800000
#define DD 64
#define BR 128   // rows per GEMM block (8 warps x 16 rows)
#define NB ((NN + 255) / 256)   // 196 scan blocks

// ---------------- device scratch (static, no allocation) ----------------
__device__ int   g_flag;
__device__ int   g_cnt[NN];
__device__ int   g_rowptr[NN + 1];
__device__ int   g_fill[NN];
__device__ int   g_bsum[NB];
__device__ unsigned short g_srcs16[EE];
__device__ unsigned short g_dst16[EE];
__device__ float g_pe[EE];                                  // per-edge exp
__device__ float g_z[NN];                                   // per-dst softmax sum
__device__ __align__(16) unsigned short g_xh[NN * DD];      // x hi (bf16 bits)
__device__ __align__(16) unsigned short g_xl[NN * DD];      // x lo (bf16 bits)
__device__ __align__(16) unsigned short g_Wh[8 * DD * DD];  // W^T hi, 8 slots
__device__ __align__(16) unsigned short g_Wl[8 * DD * DD];  // W^T lo
__device__ __align__(16) __half g_hh[NN * DD];              // per-conv h (fp16)
__device__ float g_ssrc[NN];
__device__ float g_sdst[NN];

__device__ __forceinline__ void split_bf16(float v, unsigned short& hi, unsigned short& lo) {
    __nv_bfloat16 h = __float2bfloat16(v);
    float r = v - __bfloat162float(h);
    __nv_bfloat16 l = __float2bfloat16(r);
    hi = *reinterpret_cast<unsigned short*>(&h);
    lo = *reinterpret_cast<unsigned short*>(&l);
}

// ---------------- launch 0: init (detect + zero + cvt feat + cvt W) -----
__global__ void k_init(const int* __restrict__ raw,
                       const float* __restrict__ feat,
                       const float* __restrict__ W1,
                       const float* __restrict__ W2) {
    int i = blockIdx.x * blockDim.x + threadIdx.x;
    if (i < NN * DD) split_bf16(feat[i], g_xh[i], g_xl[i]);
    if (i < NN) g_cnt[i] = 0;
    if (i < 8 * DD * DD) {
        int g = i >> 12;
        int idx = i & 4095;
        int k = idx >> 6, c = idx & 63;
        const float* W = (g < 4) ? W1 : W2;
        float v = W[(g & 3) * DD * DD + k * DD + c];
        split_bf16(v, g_Wh[g * DD * DD + c * DD + k], g_Wl[g * DD * DD + c * DD + k]);
    }
    if (blockIdx.x == 0) {
        __shared__ int ok;
        if (threadIdx.x == 0) ok = 1;
        __syncthreads();
        for (int j = threadIdx.x; j < 4096; j += blockDim.x)
            if (raw[2 * j + 1] != 0) ok = 0;
        __syncthreads();
        if (threadIdx.x == 0) g_flag = ok;
    }
}

// ---------------- histogram of dst ----------------
__global__ void k_hist(const void* __restrict__ raw, int E) {
    int base = (blockIdx.x * blockDim.x + threadIdx.x) * 4;
    if (g_flag) {
        const long long* p = (const long long*)raw + E;
#pragma unroll
        for (int u = 0; u < 4; u++) { int j = base + u; if (j < E) atomicAdd(&g_cnt[(int)p[j]], 1); }
    } else {
        const int* p = (const int*)raw + E;
#pragma unroll
        for (int u = 0; u < 4; u++) { int j = base + u; if (j < E) atomicAdd(&g_cnt[p[j]], 1); }
    }
}

// ---------------- 2-phase parallel scan ----------------
__global__ void k_scanA() {
    __shared__ int sh[256];
    int t = threadIdx.x;
    int i = blockIdx.x * 256 + t;
    int v = (i < NN) ? g_cnt[i] : 0;
    sh[t] = v;
    __syncthreads();
#pragma unroll
    for (int off = 1; off < 256; off <<= 1) {
        int u = (t >= off) ? sh[t - off] : 0;
        __syncthreads();
        sh[t] += u;
        __syncthreads();
    }
    if (i < NN) g_rowptr[i] = sh[t] - v;
    if (t == 255) g_bsum[blockIdx.x] = sh[255];
}

__global__ void k_scanC(int E) {
    __shared__ int wsum[8];
    __shared__ int off;
    int t = threadIdx.x;
    int partial = 0;
    for (int j = t; j < blockIdx.x; j += 256) partial += g_bsum[j];
#pragma unroll
    for (int o = 16; o; o >>= 1) partial += __shfl_xor_sync(0xffffffffu, partial, o);
    if ((t & 31) == 0) wsum[t >> 5] = partial;
    __syncthreads();
    if (t == 0) {
        int s = 0;
#pragma unroll
        for (int i = 0; i < 8; i++) s += wsum[i];
        off = s;
    }
    __syncthreads();
    int i = blockIdx.x * 256 + t;
    if (i < NN) {
        int r = g_rowptr[i] + off;
        g_rowptr[i] = r;
        g_fill[i] = r;
    }
    if (i == 0) g_rowptr[NN] = E;
}

// ---------------- scatter into CSR (src + dst) ----------------
__global__ void k_scatter(const void* __restrict__ raw, int E) {
    int base = (blockIdx.x * blockDim.x + threadIdx.x) * 4;
    if (g_flag) {
        const long long* p = (const long long*)raw;
#pragma unroll
        for (int u = 0; u < 4; u++) {
            int j = base + u;
            if (j < E) {
                int s = (int)p[j], d = (int)p[E + j];
                int pos = atomicAdd(&g_fill[d], 1);
                g_srcs16[pos] = (unsigned short)s;
                g_dst16[pos] = (unsigned short)d;
            }
        }
    } else {
        const int* p = (const int*)raw;
#pragma unroll
        for (int u = 0; u < 4; u++) {
            int j = base + u;
            if (j < E) {
                int s = p[j], d = p[E + j];
                int pos = atomicAdd(&g_fill[d], 1);
                g_srcs16[pos] = (unsigned short)s;
                g_dst16[pos] = (unsigned short)d;
            }
        }
    }
}

// ---------------- tensor-core GEMM (8 warps, dynamic smem) --------------
__global__ void __launch_bounds__(256) k_gemm(
        int g, const float* __restrict__ a_s, const float* __restrict__ a_d) {
    extern __shared__ __align__(16) char smem[];
    unsigned short (*Ah)[72] = (unsigned short(*)[72])(smem);
    unsigned short (*Al)[72] = (unsigned short(*)[72])(smem + 18432);
    unsigned short (*Bh)[72] = (unsigned short(*)[72])(smem + 36864);
    unsigned short (*Bl)[72] = (unsigned short(*)[72])(smem + 46080);
    int t = threadIdx.x;
    int rb = blockIdx.x * BR;

    for (int i = t; i < 512; i += 256) {
        int c = i >> 3, q = i & 7;
        ((uint4*)&Bh[c][0])[q] = ((const uint4*)(g_Wh + g * DD * DD + c * DD))[q];
        ((uint4*)&Bl[c][0])[q] = ((const uint4*)(g_Wl + g * DD * DD + c * DD))[q];
    }
    for (int i = t; i < 1024; i += 256) {
        int r = i >> 3, q = i & 7;
        int gr = rb + r; if (gr >= NN) gr = 0;
        ((uint4*)&Ah[r][0])[q] = ((const uint4*)(g_xh + (size_t)gr * DD))[q];
        ((uint4*)&Al[r][0])[q] = ((const uint4*)(g_xl + (size_t)gr * DD))[q];
    }
    __syncthreads();

    int lane = t & 31, wid = t >> 5;
    int gid = lane >> 2, tig = lane & 3;

    float acc[8][4];
#pragma unroll
    for (int nt = 0; nt < 8; nt++)
#pragma unroll
        for (int q = 0; q < 4; q++) acc[nt][q] = 0.f;

#pragma unroll
    for (int ks = 0; ks < 4; ks++) {
        int k0 = ks * 16 + 2 * tig;
        int r0 = wid * 16 + gid;
        uint32_t ahi[4], alo[4];
        ahi[0] = *(const uint32_t*)&Ah[r0][k0];
        ahi[1] = *(const uint32_t*)&Ah[r0 + 8][k0];
        ahi[2] = *(const uint32_t*)&Ah[r0][k0 + 8];
        ahi[3] = *(const uint32_t*)&Ah[r0 + 8][k0 + 8];
        alo[0] = *(const uint32_t*)&Al[r0][k0];
        alo[1] = *(const uint32_t*)&Al[r0 + 8][k0];
        alo[2] = *(const uint32_t*)&Al[r0][k0 + 8];
        alo[3] = *(const uint32_t*)&Al[r0 + 8][k0 + 8];
#pragma unroll
        for (int nt = 0; nt < 8; nt++) {
            int n = nt * 8 + gid;
            uint32_t bhi[2], blo[2];
            bhi[0] = *(const uint32_t*)&Bh[n][k0];
            bhi[1] = *(const uint32_t*)&Bh[n][k0 + 8];
            blo[0] = *(const uint32_t*)&Bl[n][k0];
            blo[1] = *(const uint32_t*)&Bl[n][k0 + 8];
            asm volatile(
                "mma.sync.aligned.m16n8k16.row.col.f32.bf16.bf16.f32 "
                "{%0,%1,%2,%3}, {%4,%5,%6,%7}, {%8,%9}, {%0,%1,%2,%3};"
                : "+f"(acc[nt][0]), "+f"(acc[nt][1]), "+f"(acc[nt][2]), "+f"(acc[nt][3])
                : "r"(ahi[0]), "r"(ahi[1]), "r"(ahi[2]), "r"(ahi[3]),
                  "r"(bhi[0]), "r"(bhi[1]));
            asm volatile(
                "mma.sync.aligned.m16n8k16.row.col.f32.bf16.bf16.f32 "
                "{%0,%1,%2,%3}, {%4,%5,%6,%7}, {%8,%9}, {%0,%1,%2,%3};"
                : "+f"(acc[nt][0]), "+f"(acc[nt][1]), "+f"(acc[nt][2]), "+f"(acc[nt][3])
                : "r"(ahi[0]), "r"(ahi[1]), "r"(ahi[2]), "r"(ahi[3]),
                  "r"(blo[0]), "r"(blo[1]));
            asm volatile(
                "mma.sync.aligned.m16n8k16.row.col.f32.bf16.bf16.f32 "
                "{%0,%1,%2,%3}, {%4,%5,%6,%7}, {%8,%9}, {%0,%1,%2,%3};"
                : "+f"(acc[nt][0]), "+f"(acc[nt][1]), "+f"(acc[nt][2]), "+f"(acc[nt][3])
                : "r"(alo[0]), "r"(alo[1]), "r"(alo[2]), "r"(alo[3]),
                  "r"(bhi[0]), "r"(bhi[1]));
        }
    }

    float2 asv[8], adv[8];
#pragma unroll
    for (int nt = 0; nt < 8; nt++) {
        asv[nt] = ((const float2*)a_s)[nt * 4 + tig];
        adv[nt] = ((const float2*)a_d)[nt * 4 + tig];
    }
    int r0 = rb + wid * 16 + gid;
    float ss0 = 0.f, sd0 = 0.f, ss1 = 0.f, sd1 = 0.f;
#pragma unroll
    for (int nt = 0; nt < 8; nt++) {
        ss0 = fmaf(acc[nt][0], asv[nt].x, fmaf(acc[nt][1], asv[nt].y, ss0));
        sd0 = fmaf(acc[nt][0], adv[nt].x, fmaf(acc[nt][1], adv[nt].y, sd0));
        ss1 = fmaf(acc[nt][2], asv[nt].x, fmaf(acc[nt][3], asv[nt].y, ss1));
        sd1 = fmaf(acc[nt][2], adv[nt].x, fmaf(acc[nt][3], adv[nt].y, sd1));
    }
#pragma unroll
    for (int o = 1; o <= 2; o <<= 1) {
        ss0 += __shfl_xor_sync(0xffffffffu, ss0, o);
        sd0 += __shfl_xor_sync(0xffffffffu, sd0, o);
        ss1 += __shfl_xor_sync(0xffffffffu, ss1, o);
        sd1 += __shfl_xor_sync(0xffffffffu, sd1, o);
    }
    bool ok0 = (r0 < NN), ok1 = (r0 + 8 < NN);
#pragma unroll
    for (int nt = 0; nt < 8; nt++) {
        int col = nt * 8 + 2 * tig;
        if (ok0)
            *(__half2*)(g_hh + (size_t)r0 * DD + col) =
                __floats2half2_rn(acc[nt][0], acc[nt][1]);
        if (ok1)
            *(__half2*)(g_hh + (size_t)(r0 + 8) * DD + col) =
                __floats2half2_rn(acc[nt][2], acc[nt][3]);
    }
    if (tig == 0) {
        if (ok0) { g_ssrc[r0] = ss0; g_sdst[r0] = sd0; g_z[r0] = 0.f; }
        if (ok1) { g_ssrc[r0 + 8] = ss1; g_sdst[r0 + 8] = sd1; g_z[r0 + 8] = 0.f; }
    }
}

// ---------------- aggA: edge-parallel exp + z reduction (REDG) ----------
__global__ void k_aggA(int E) {
    int base = (blockIdx.x * blockDim.x + threadIdx.x) * 4;
#pragma unroll
    for (int u = 0; u < 4; u++) {
        int j = base + u;
        if (j < E) {
            int s = g_srcs16[j];
            int d = g_dst16[j];
            float e = g_ssrc[s] + g_sdst[d];
            e = (e > 0.f) ? e : 0.2f * e;
            float p = __expf(fminf(e, 60.f));
            g_pe[j] = p;
            atomicAdd(&g_z[d], p);     // no return value -> REDG
        }
    }
}

// ---------------- aggB: node-parallel weighted gather --------------------
// One warp per dst node. Inner loop: NO dependent loads, NO exp — only
// pe[j] (broadcast) and the coalesced h gather. inv applied once at end.
__global__ void __launch_bounds__(256) k_aggB(float* __restrict__ yext,
                                              int is_last, int do_elu) {
    int w = (blockIdx.x * blockDim.x + threadIdx.x) >> 5;
    int lane = threadIdx.x & 31;
    if (w >= NN) return;
    int start = g_rowptr[w], end = g_rowptr[w + 1];
    float inv = 1.f / (g_z[w] + 1e-16f);

    int q = lane >> 3, l8 = lane & 7;
    float acc[8];
#pragma unroll
    for (int i = 0; i < 8; i++) acc[i] = 0.f;
    const uint4* h16 = (const uint4*)g_hh;
#pragma unroll 4
    for (int j = start + q; j < end; j += 4) {
        int s = g_srcs16[j];
        float p = g_pe[j];
        uint4 hv = h16[(size_t)s * 8 + l8];
        float2 f0 = __half22float2(*reinterpret_cast<const __half2*>(&hv.x));
        float2 f1 = __half22float2(*reinterpret_cast<const __half2*>(&hv.y));
        float2 f2 = __half22float2(*reinterpret_cast<const __half2*>(&hv.z));
        float2 f3 = __half22float2(*reinterpret_cast<const __half2*>(&hv.w));
        acc[0] = fmaf(f0.x, p, acc[0]);
        acc[1] = fmaf(f0.y, p, acc[1]);
        acc[2] = fmaf(f1.x, p, acc[2]);
        acc[3] = fmaf(f1.y, p, acc[3]);
        acc[4] = fmaf(f2.x, p, acc[4]);
        acc[5] = fmaf(f2.y, p, acc[5]);
        acc[6] = fmaf(f3.x, p, acc[6]);
        acc[7] = fmaf(f3.y, p, acc[7]);
    }
#pragma unroll
    for (int i = 0; i < 8; i++) {
        acc[i] += __shfl_xor_sync(0xffffffffu, acc[i], 8);
        acc[i] += __shfl_xor_sync(0xffffffffu, acc[i], 16);
    }
    if (q == 0) {
#pragma unroll
        for (int i = 0; i < 8; i++) acc[i] *= inv;
        if (do_elu) {
#pragma unroll
            for (int i = 0; i < 8; i++)
                acc[i] = (acc[i] > 0.f) ? acc[i] : (__expf(acc[i]) - 1.f);
        }
        if (is_last) {
            float4 v0 = make_float4(acc[0], acc[1], acc[2], acc[3]);
            float4 v1 = make_float4(acc[4], acc[5], acc[6], acc[7]);
            ((float4*)yext)[(size_t)w * 16 + l8 * 2]     = v0;
            ((float4*)yext)[(size_t)w * 16 + l8 * 2 + 1] = v1;
        } else {
            ushort4 hh0, ll0, hh1, ll1;
            split_bf16(acc[0], hh0.x, ll0.x);
            split_bf16(acc[1], hh0.y, ll0.y);
            split_bf16(acc[2], hh0.z, ll0.z);
            split_bf16(acc[3], hh0.w, ll0.w);
            split_bf16(acc[4], hh1.x, ll1.x);
            split_bf16(acc[5], hh1.y, ll1.y);
            split_bf16(acc[6], hh1.z, ll1.z);
            split_bf16(acc[7], hh1.w, ll1.w);
            *(ushort4*)(g_xh + (size_t)w * DD + l8 * 8)     = hh0;
            *(ushort4*)(g_xh + (size_t)w * DD + l8 * 8 + 4) = hh1;
            *(ushort4*)(g_xl + (size_t)w * DD + l8 * 8)     = ll0;
            *(ushort4*)(g_xl + (size_t)w * DD + l8 * 8 + 4) = ll1;
        }
    }
}

// ---------------- launch ----------------
extern "C" void kernel_launch(void* const* d_in, const int* in_sizes, int n_in,
                              void* d_out, int out_size) {
    const float* feat  = (const float*)d_in[0];
    const void*  eidx  = d_in[1];
    const float* W1    = (const float*)d_in[2];
    const float* a_s1  = (const float*)d_in[3];
    const float* a_d1  = (const float*)d_in[4];
    const float* W2    = (const float*)d_in[5];
    const float* a_s2  = (const float*)d_in[6];
    const float* a_d2  = (const float*)d_in[7];
    float* out = (float*)d_out;

    int E = in_sizes[1] / 2;

    static int smem_set = 0;
    if (!smem_set) {
        cudaFuncSetAttribute(k_gemm, cudaFuncAttributeMaxDynamicSharedMemorySize, 55296);
        smem_set = 1;
    }

    const int gemm_grid = (NN + BR - 1) / BR;
    const int aggB_grid = (NN * 32 + 255) / 256;
    const int edge_grid = (E / 4 + 255) / 256;

    k_init<<<(NN * DD + 255) / 256, 256>>>((const int*)eidx, feat, W1, W2);  // 0
    k_gemm<<<gemm_grid, 256, 55296>>>(0, a_s1, a_d1);                        // 1
    k_hist<<<edge_grid, 256>>>(eidx, E);                                     // 2
    k_scanA<<<NB, 256>>>();                                                  // 3
    k_scanC<<<NB, 256>>>(E);                                                 // 4
    k_scatter<<<edge_grid, 256>>>(eidx, E);                                  // 5
    k_aggA<<<edge_grid, 256>>>(E);                                           // 6
    k_aggB<<<aggB_grid, 256>>>(out, 0, 0);                                   // 7

    for (int layer = 0; layer < 2; layer++) {
        const float* as = layer ? a_s2 : a_s1;
        const float* ad = layer ? a_d2 : a_d1;
        for (int head = (layer == 0 ? 1 : 0); head < 4; head++) {
            int g = layer * 4 + head;
            int last = (layer == 1 && head == 3);
            int eol  = (head == 3);
            k_gemm<<<gemm_grid, 256, 55296>>>(g, as + head * DD, ad + head * DD);
            k_aggA<<<edge_grid, 256>>>(E);
            k_aggB<<<aggB_grid, 256>>>(out, last, eol);
        }
    }
}

// round 13
// speedup vs baseline: 1.5601x; 1.0087x over previous
#include <cuda_runtime.h>
#include <cuda_fp16.h>
#include <cuda_bf16.h>
#include <stdint.h>

#define NN 50000
#define EE 800000
#define DD 64
#define BR 128   // rows per GEMM block (8 warps x 16 rows)
#define NB ((NN + 255) / 256)   // 196 scan blocks

// ---------------- device scratch (static, no allocation) ----------------
__device__ int   g_flag;
__device__ int   g_cnt[NN];
__device__ int   g_rowptr[NN + 1];
__device__ int   g_fill[NN];
__device__ int   g_bsum[NB];
__device__ unsigned short g_srcs16[EE];
__device__ unsigned short g_dst16[EE];
__device__ float g_pe[EE];                                  // per-edge exp
__device__ float g_z[NN];                                   // per-dst softmax sum
__device__ __align__(16) unsigned short g_xh[NN * DD];      // x hi (bf16 bits)
__device__ __align__(16) unsigned short g_xl[NN * DD];      // x lo (bf16 bits)
__device__ __align__(16) unsigned short g_Wh[8 * DD * DD];  // W^T hi, 8 slots
__device__ __align__(16) unsigned short g_Wl[8 * DD * DD];  // W^T lo
__device__ __align__(16) __half g_hh[NN * DD];              // per-conv h (fp16)
__device__ float g_ssrc[NN];
__device__ float g_sdst[NN];

__device__ __forceinline__ void split_bf16(float v, unsigned short& hi, unsigned short& lo) {
    __nv_bfloat16 h = __float2bfloat16(v);
    float r = v - __bfloat162float(h);
    __nv_bfloat16 l = __float2bfloat16(r);
    hi = *reinterpret_cast<unsigned short*>(&h);
    lo = *reinterpret_cast<unsigned short*>(&l);
}

// ---------------- init0: zero counters + dtype detect (tiny) ------------
__global__ void k_init0(const int* __restrict__ raw) {
    int i = blockIdx.x * blockDim.x + threadIdx.x;
    if (i < NN) g_cnt[i] = 0;
    if (blockIdx.x == 0) {
        __shared__ int ok;
        if (threadIdx.x == 0) ok = 1;
        __syncthreads();
        for (int j = threadIdx.x; j < 4096; j += blockDim.x)
            if (raw[2 * j + 1] != 0) ok = 0;
        __syncthreads();
        if (threadIdx.x == 0) g_flag = ok;
    }
}

// ---------------- cvt: feat + W -> split bf16 ----------------------------
__global__ void k_cvt(const float* __restrict__ feat,
                      const float* __restrict__ W1,
                      const float* __restrict__ W2) {
    int i = blockIdx.x * blockDim.x + threadIdx.x;
    if (i < NN * DD) split_bf16(feat[i], g_xh[i], g_xl[i]);
    if (i < 8 * DD * DD) {
        int g = i >> 12;
        int idx = i & 4095;
        int k = idx >> 6, c = idx & 63;
        const float* W = (g < 4) ? W1 : W2;
        float v = W[(g & 3) * DD * DD + k * DD + c];
        split_bf16(v, g_Wh[g * DD * DD + c * DD + k], g_Wl[g * DD * DD + c * DD + k]);
    }
}

// ---------------- histogram of dst, 8 edges/thread ----------------------
__global__ void k_hist(const void* __restrict__ raw, int E) {
    int base = (blockIdx.x * blockDim.x + threadIdx.x) * 8;
    if (g_flag) {
        const long long* p = (const long long*)raw + E;
#pragma unroll
        for (int u = 0; u < 8; u++) { int j = base + u; if (j < E) atomicAdd(&g_cnt[(int)p[j]], 1); }
    } else {
        const int* p = (const int*)raw + E;
#pragma unroll
        for (int u = 0; u < 8; u++) { int j = base + u; if (j < E) atomicAdd(&g_cnt[p[j]], 1); }
    }
}

// ---------------- 2-phase parallel scan ----------------
__global__ void k_scanA() {
    __shared__ int sh[256];
    int t = threadIdx.x;
    int i = blockIdx.x * 256 + t;
    int v = (i < NN) ? g_cnt[i] : 0;
    sh[t] = v;
    __syncthreads();
#pragma unroll
    for (int off = 1; off < 256; off <<= 1) {
        int u = (t >= off) ? sh[t - off] : 0;
        __syncthreads();
        sh[t] += u;
        __syncthreads();
    }
    if (i < NN) g_rowptr[i] = sh[t] - v;
    if (t == 255) g_bsum[blockIdx.x] = sh[255];
}

__global__ void k_scanC(int E) {
    __shared__ int wsum[8];
    __shared__ int off;
    int t = threadIdx.x;
    int partial = 0;
    for (int j = t; j < blockIdx.x; j += 256) partial += g_bsum[j];
#pragma unroll
    for (int o = 16; o; o >>= 1) partial += __shfl_xor_sync(0xffffffffu, partial, o);
    if ((t & 31) == 0) wsum[t >> 5] = partial;
    __syncthreads();
    if (t == 0) {
        int s = 0;
#pragma unroll
        for (int i = 0; i < 8; i++) s += wsum[i];
        off = s;
    }
    __syncthreads();
    int i = blockIdx.x * 256 + t;
    if (i < NN) {
        int r = g_rowptr[i] + off;
        g_rowptr[i] = r;
        g_fill[i] = r;
    }
    if (i == 0) g_rowptr[NN] = E;
}

// ---------------- scatter into CSR (src + dst), 8 edges/thread ----------
__global__ void k_scatter(const void* __restrict__ raw, int E) {
    int base = (blockIdx.x * blockDim.x + threadIdx.x) * 8;
    if (g_flag) {
        const long long* p = (const long long*)raw;
#pragma unroll
        for (int u = 0; u < 8; u++) {
            int j = base + u;
            if (j < E) {
                int s = (int)p[j], d = (int)p[E + j];
                int pos = atomicAdd(&g_fill[d], 1);
                g_srcs16[pos] = (unsigned short)s;
                g_dst16[pos] = (unsigned short)d;
            }
        }
    } else {
        const int* p = (const int*)raw;
#pragma unroll
        for (int u = 0; u < 8; u++) {
            int j = base + u;
            if (j < E) {
                int s = p[j], d = p[E + j];
                int pos = atomicAdd(&g_fill[d], 1);
                g_srcs16[pos] = (unsigned short)s;
                g_dst16[pos] = (unsigned short)d;
            }
        }
    }
}

// ---------------- tensor-core GEMM (8 warps, dynamic smem) --------------
__global__ void __launch_bounds__(256) k_gemm(
        int g, const float* __restrict__ a_s, const float* __restrict__ a_d) {
    extern __shared__ __align__(16) char smem[];
    unsigned short (*Ah)[72] = (unsigned short(*)[72])(smem);
    unsigned short (*Al)[72] = (unsigned short(*)[72])(smem + 18432);
    unsigned short (*Bh)[72] = (unsigned short(*)[72])(smem + 36864);
    unsigned short (*Bl)[72] = (unsigned short(*)[72])(smem + 46080);
    int t = threadIdx.x;
    int rb = blockIdx.x * BR;

    for (int i = t; i < 512; i += 256) {
        int c = i >> 3, q = i & 7;
        ((uint4*)&Bh[c][0])[q] = ((const uint4*)(g_Wh + g * DD * DD + c * DD))[q];
        ((uint4*)&Bl[c][0])[q] = ((const uint4*)(g_Wl + g * DD * DD + c * DD))[q];
    }
    for (int i = t; i < 1024; i += 256) {
        int r = i >> 3, q = i & 7;
        int gr = rb + r; if (gr >= NN) gr = 0;
        ((uint4*)&Ah[r][0])[q] = ((const uint4*)(g_xh + (size_t)gr * DD))[q];
        ((uint4*)&Al[r][0])[q] = ((const uint4*)(g_xl + (size_t)gr * DD))[q];
    }
    __syncthreads();

    int lane = t & 31, wid = t >> 5;
    int gid = lane >> 2, tig = lane & 3;

    float acc[8][4];
#pragma unroll
    for (int nt = 0; nt < 8; nt++)
#pragma unroll
        for (int q = 0; q < 4; q++) acc[nt][q] = 0.f;

#pragma unroll
    for (int ks = 0; ks < 4; ks++) {
        int k0 = ks * 16 + 2 * tig;
        int r0 = wid * 16 + gid;
        uint32_t ahi[4], alo[4];
        ahi[0] = *(const uint32_t*)&Ah[r0][k0];
        ahi[1] = *(const uint32_t*)&Ah[r0 + 8][k0];
        ahi[2] = *(const uint32_t*)&Ah[r0][k0 + 8];
        ahi[3] = *(const uint32_t*)&Ah[r0 + 8][k0 + 8];
        alo[0] = *(const uint32_t*)&Al[r0][k0];
        alo[1] = *(const uint32_t*)&Al[r0 + 8][k0];
        alo[2] = *(const uint32_t*)&Al[r0][k0 + 8];
        alo[3] = *(const uint32_t*)&Al[r0 + 8][k0 + 8];
#pragma unroll
        for (int nt = 0; nt < 8; nt++) {
            int n = nt * 8 + gid;
            uint32_t bhi[2], blo[2];
            bhi[0] = *(const uint32_t*)&Bh[n][k0];
            bhi[1] = *(const uint32_t*)&Bh[n][k0 + 8];
            blo[0] = *(const uint32_t*)&Bl[n][k0];
            blo[1] = *(const uint32_t*)&Bl[n][k0 + 8];
            asm volatile(
                "mma.sync.aligned.m16n8k16.row.col.f32.bf16.bf16.f32 "
                "{%0,%1,%2,%3}, {%4,%5,%6,%7}, {%8,%9}, {%0,%1,%2,%3};"
                : "+f"(acc[nt][0]), "+f"(acc[nt][1]), "+f"(acc[nt][2]), "+f"(acc[nt][3])
                : "r"(ahi[0]), "r"(ahi[1]), "r"(ahi[2]), "r"(ahi[3]),
                  "r"(bhi[0]), "r"(bhi[1]));
            asm volatile(
                "mma.sync.aligned.m16n8k16.row.col.f32.bf16.bf16.f32 "
                "{%0,%1,%2,%3}, {%4,%5,%6,%7}, {%8,%9}, {%0,%1,%2,%3};"
                : "+f"(acc[nt][0]), "+f"(acc[nt][1]), "+f"(acc[nt][2]), "+f"(acc[nt][3])
                : "r"(ahi[0]), "r"(ahi[1]), "r"(ahi[2]), "r"(ahi[3]),
                  "r"(blo[0]), "r"(blo[1]));
            asm volatile(
                "mma.sync.aligned.m16n8k16.row.col.f32.bf16.bf16.f32 "
                "{%0,%1,%2,%3}, {%4,%5,%6,%7}, {%8,%9}, {%0,%1,%2,%3};"
                : "+f"(acc[nt][0]), "+f"(acc[nt][1]), "+f"(acc[nt][2]), "+f"(acc[nt][3])
                : "r"(alo[0]), "r"(alo[1]), "r"(alo[2]), "r"(alo[3]),
                  "r"(bhi[0]), "r"(bhi[1]));
        }
    }

    float2 asv[8], adv[8];
#pragma unroll
    for (int nt = 0; nt < 8; nt++) {
        asv[nt] = ((const float2*)a_s)[nt * 4 + tig];
        adv[nt] = ((const float2*)a_d)[nt * 4 + tig];
    }
    int r0 = rb + wid * 16 + gid;
    float ss0 = 0.f, sd0 = 0.f, ss1 = 0.f, sd1 = 0.f;
#pragma unroll
    for (int nt = 0; nt < 8; nt++) {
        ss0 = fmaf(acc[nt][0], asv[nt].x, fmaf(acc[nt][1], asv[nt].y, ss0));
        sd0 = fmaf(acc[nt][0], adv[nt].x, fmaf(acc[nt][1], adv[nt].y, sd0));
        ss1 = fmaf(acc[nt][2], asv[nt].x, fmaf(acc[nt][3], asv[nt].y, ss1));
        sd1 = fmaf(acc[nt][2], adv[nt].x, fmaf(acc[nt][3], adv[nt].y, sd1));
    }
#pragma unroll
    for (int o = 1; o <= 2; o <<= 1) {
        ss0 += __shfl_xor_sync(0xffffffffu, ss0, o);
        sd0 += __shfl_xor_sync(0xffffffffu, sd0, o);
        ss1 += __shfl_xor_sync(0xffffffffu, ss1, o);
        sd1 += __shfl_xor_sync(0xffffffffu, sd1, o);
    }
    bool ok0 = (r0 < NN), ok1 = (r0 + 8 < NN);
#pragma unroll
    for (int nt = 0; nt < 8; nt++) {
        int col = nt * 8 + 2 * tig;
        if (ok0)
            *(__half2*)(g_hh + (size_t)r0 * DD + col) =
                __floats2half2_rn(acc[nt][0], acc[nt][1]);
        if (ok1)
            *(__half2*)(g_hh + (size_t)(r0 + 8) * DD + col) =
                __floats2half2_rn(acc[nt][2], acc[nt][3]);
    }
    if (tig == 0) {
        if (ok0) { g_ssrc[r0] = ss0; g_sdst[r0] = sd0; g_z[r0] = 0.f; }
        if (ok1) { g_ssrc[r0 + 8] = ss1; g_sdst[r0 + 8] = sd1; g_z[r0 + 8] = 0.f; }
    }
}

// ---------------- aggA: edge-parallel exp + z reduction (REDG) ----------
__global__ void k_aggA(int E) {
    int base = (blockIdx.x * blockDim.x + threadIdx.x) * 4;
#pragma unroll
    for (int u = 0; u < 4; u++) {
        int j = base + u;
        if (j < E) {
            int s = g_srcs16[j];
            int d = g_dst16[j];
            float e = g_ssrc[s] + g_sdst[d];
            e = (e > 0.f) ? e : 0.2f * e;
            float p = __expf(fminf(e, 60.f));
            g_pe[j] = p;
            atomicAdd(&g_z[d], p);     // no return value -> REDG
        }
    }
}

// ---------------- aggB: node-parallel weighted gather --------------------
__global__ void __launch_bounds__(256) k_aggB(float* __restrict__ yext,
                                              int is_last, int do_elu) {
    int w = (blockIdx.x * blockDim.x + threadIdx.x) >> 5;
    int lane = threadIdx.x & 31;
    if (w >= NN) return;
    int start = g_rowptr[w], end = g_rowptr[w + 1];
    float inv = 1.f / (g_z[w] + 1e-16f);

    int q = lane >> 3, l8 = lane & 7;
    float acc[8];
#pragma unroll
    for (int i = 0; i < 8; i++) acc[i] = 0.f;
    const uint4* h16 = (const uint4*)g_hh;
#pragma unroll 4
    for (int j = start + q; j < end; j += 4) {
        int s = g_srcs16[j];
        float p = g_pe[j];
        uint4 hv = h16[(size_t)s * 8 + l8];
        float2 f0 = __half22float2(*reinterpret_cast<const __half2*>(&hv.x));
        float2 f1 = __half22float2(*reinterpret_cast<const __half2*>(&hv.y));
        float2 f2 = __half22float2(*reinterpret_cast<const __half2*>(&hv.z));
        float2 f3 = __half22float2(*reinterpret_cast<const __half2*>(&hv.w));
        acc[0] = fmaf(f0.x, p, acc[0]);
        acc[1] = fmaf(f0.y, p, acc[1]);
        acc[2] = fmaf(f1.x, p, acc[2]);
        acc[3] = fmaf(f1.y, p, acc[3]);
        acc[4] = fmaf(f2.x, p, acc[4]);
        acc[5] = fmaf(f2.y, p, acc[5]);
        acc[6] = fmaf(f3.x, p, acc[6]);
        acc[7] = fmaf(f3.y, p, acc[7]);
    }
#pragma unroll
    for (int i = 0; i < 8; i++) {
        acc[i] += __shfl_xor_sync(0xffffffffu, acc[i], 8);
        acc[i] += __shfl_xor_sync(0xffffffffu, acc[i], 16);
    }
    if (q == 0) {
#pragma unroll
        for (int i = 0; i < 8; i++) acc[i] *= inv;
        if (do_elu) {
#pragma unroll
            for (int i = 0; i < 8; i++)
                acc[i] = (acc[i] > 0.f) ? acc[i] : (__expf(acc[i]) - 1.f);
        }
        if (is_last) {
            float4 v0 = make_float4(acc[0], acc[1], acc[2], acc[3]);
            float4 v1 = make_float4(acc[4], acc[5], acc[6], acc[7]);
            ((float4*)yext)[(size_t)w * 16 + l8 * 2]     = v0;
            ((float4*)yext)[(size_t)w * 16 + l8 * 2 + 1] = v1;
        } else {
            ushort4 hh0, ll0, hh1, ll1;
            split_bf16(acc[0], hh0.x, ll0.x);
            split_bf16(acc[1], hh0.y, ll0.y);
            split_bf16(acc[2], hh0.z, ll0.z);
            split_bf16(acc[3], hh0.w, ll0.w);
            split_bf16(acc[4], hh1.x, ll1.x);
            split_bf16(acc[5], hh1.y, ll1.y);
            split_bf16(acc[6], hh1.z, ll1.z);
            split_bf16(acc[7], hh1.w, ll1.w);
            *(ushort4*)(g_xh + (size_t)w * DD + l8 * 8)     = hh0;
            *(ushort4*)(g_xh + (size_t)w * DD + l8 * 8 + 4) = hh1;
            *(ushort4*)(g_xl + (size_t)w * DD + l8 * 8)     = ll0;
            *(ushort4*)(g_xl + (size_t)w * DD + l8 * 8 + 4) = ll1;
        }
    }
}

// ---------------- launch ----------------
extern "C" void kernel_launch(void* const* d_in, const int* in_sizes, int n_in,
                              void* d_out, int out_size) {
    const float* feat  = (const float*)d_in[0];
    const void*  eidx  = d_in[1];
    const float* W1    = (const float*)d_in[2];
    const float* a_s1  = (const float*)d_in[3];
    const float* a_d1  = (const float*)d_in[4];
    const float* W2    = (const float*)d_in[5];
    const float* a_s2  = (const float*)d_in[6];
    const float* a_d2  = (const float*)d_in[7];
    float* out = (float*)d_out;

    int E = in_sizes[1] / 2;

    static int init_done = 0;
    static cudaStream_t s_side;
    static cudaEvent_t ev_fork, ev_join;
    if (!init_done) {
        cudaFuncSetAttribute(k_gemm, cudaFuncAttributeMaxDynamicSharedMemorySize, 55296);
        cudaStreamCreateWithFlags(&s_side, cudaStreamNonBlocking);
        cudaEventCreateWithFlags(&ev_fork, cudaEventDisableTiming);
        cudaEventCreateWithFlags(&ev_join, cudaEventDisableTiming);
        init_done = 1;
    }

    const int gemm_grid = (NN + BR - 1) / BR;
    const int aggB_grid = (NN * 32 + 255) / 256;
    const int e4_grid   = (E / 4 + 255) / 256;
    const int e8_grid   = (E / 8 + 255) / 256;

    // init0 (zero cnt + dtype flag) on main, then fork CSR chain to side.
    k_init0<<<(NN + 255) / 256, 256>>>((const int*)eidx);
    cudaEventRecord(ev_fork, 0);
    cudaStreamWaitEvent(s_side, ev_fork, 0);

    // side stream: CSR build (independent of cvt/gemm)
    k_hist<<<e8_grid, 256, 0, s_side>>>(eidx, E);
    k_scanA<<<NB, 256, 0, s_side>>>();
    k_scanC<<<NB, 256, 0, s_side>>>(E);
    k_scatter<<<e8_grid, 256, 0, s_side>>>(eidx, E);
    cudaEventRecord(ev_join, s_side);

    // main stream: cvt + gemm head 0 (overlaps with CSR build)
    k_cvt<<<(NN * DD + 255) / 256, 256>>>(feat, W1, W2);
    k_gemm<<<gemm_grid, 256, 55296>>>(0, a_s1, a_d1);

    // join: aggA needs both CSR (side) and gemm0 (main)
    cudaStreamWaitEvent(0, ev_join, 0);
    k_aggA<<<e4_grid, 256>>>(E);
    k_aggB<<<aggB_grid, 256>>>(out, 0, 0);

    for (int layer = 0; layer < 2; layer++) {
        const float* as = layer ? a_s2 : a_s1;
        const float* ad = layer ? a_d2 : a_d1;
        for (int head = (layer == 0 ? 1 : 0); head < 4; head++) {
            int g = layer * 4 + head;
            int last = (layer == 1 && head == 3);
            int eol  = (head == 3);
            k_gemm<<<gemm_grid, 256, 55296>>>(g, as + head * DD, ad + head * DD);
            k_aggA<<<e4_grid, 256>>>(E);
            k_aggB<<<aggB_grid, 256>>>(out, last, eol);
        }
    }
}

// round 14
// speedup vs baseline: 1.6144x; 1.0348x over previous
#include <cuda_runtime.h>
#include <cuda_fp16.h>
#include <stdint.h>

#define NN 50000
#define EE 800000
#define DD 64
#define BR 128   // rows per GEMM block (8 warps x 16 rows)
#define NB ((NN + 255) / 256)   // 196 scan blocks

// ---------------- device scratch (static, no allocation) ----------------
__device__ int   g_flag;
__device__ int   g_cnt[NN];
__device__ int   g_rowptr[NN + 1];
__device__ int   g_fill[NN];
__device__ int   g_bsum[NB];
__device__ unsigned short g_srcs16[EE];
__device__ unsigned short g_dst16[EE];
__device__ float g_pe[EE];                              // per-edge exp
__device__ float g_z[NN];                               // per-dst softmax sum
__device__ __align__(16) __half g_x[NN * DD];           // layer input (fp16)
__device__ __align__(16) __half g_W[8 * DD * DD];       // W^T (fp16), 8 slots
__device__ __align__(16) __half g_hh[NN * DD];          // per-conv h (fp16)
__device__ float g_ssrc[NN];
__device__ float g_sdst[NN];

// ---------------- init0: zero counters + dtype detect (tiny) ------------
__global__ void k_init0(const int* __restrict__ raw) {
    int i = blockIdx.x * blockDim.x + threadIdx.x;
    if (i < NN) g_cnt[i] = 0;
    if (blockIdx.x == 0) {
        __shared__ int ok;
        if (threadIdx.x == 0) ok = 1;
        __syncthreads();
        for (int j = threadIdx.x; j < 4096; j += blockDim.x)
            if (raw[2 * j + 1] != 0) ok = 0;
        __syncthreads();
        if (threadIdx.x == 0) g_flag = ok;
    }
}

// ---------------- cvt: feat + W -> fp16 (W transposed) -------------------
__global__ void k_cvt(const float* __restrict__ feat,
                      const float* __restrict__ W1,
                      const float* __restrict__ W2) {
    int i = blockIdx.x * blockDim.x + threadIdx.x;
    if (i < NN * DD) g_x[i] = __float2half_rn(feat[i]);
    if (i < 8 * DD * DD) {
        int g = i >> 12;
        int idx = i & 4095;
        int k = idx >> 6, c = idx & 63;
        const float* W = (g < 4) ? W1 : W2;
        g_W[g * DD * DD + c * DD + k] =
            __float2half_rn(W[(g & 3) * DD * DD + k * DD + c]);
    }
}

// ---------------- histogram of dst, 8 edges/thread ----------------------
__global__ void k_hist(const void* __restrict__ raw, int E) {
    int base = (blockIdx.x * blockDim.x + threadIdx.x) * 8;
    if (g_flag) {
        const long long* p = (const long long*)raw + E;
#pragma unroll
        for (int u = 0; u < 8; u++) { int j = base + u; if (j < E) atomicAdd(&g_cnt[(int)p[j]], 1); }
    } else {
        const int* p = (const int*)raw + E;
#pragma unroll
        for (int u = 0; u < 8; u++) { int j = base + u; if (j < E) atomicAdd(&g_cnt[p[j]], 1); }
    }
}

// ---------------- 2-phase parallel scan ----------------
__global__ void k_scanA() {
    __shared__ int sh[256];
    int t = threadIdx.x;
    int i = blockIdx.x * 256 + t;
    int v = (i < NN) ? g_cnt[i] : 0;
    sh[t] = v;
    __syncthreads();
#pragma unroll
    for (int off = 1; off < 256; off <<= 1) {
        int u = (t >= off) ? sh[t - off] : 0;
        __syncthreads();
        sh[t] += u;
        __syncthreads();
    }
    if (i < NN) g_rowptr[i] = sh[t] - v;
    if (t == 255) g_bsum[blockIdx.x] = sh[255];
}

__global__ void k_scanC(int E) {
    __shared__ int wsum[8];
    __shared__ int off;
    int t = threadIdx.x;
    int partial = 0;
    for (int j = t; j < blockIdx.x; j += 256) partial += g_bsum[j];
#pragma unroll
    for (int o = 16; o; o >>= 1) partial += __shfl_xor_sync(0xffffffffu, partial, o);
    if ((t & 31) == 0) wsum[t >> 5] = partial;
    __syncthreads();
    if (t == 0) {
        int s = 0;
#pragma unroll
        for (int i = 0; i < 8; i++) s += wsum[i];
        off = s;
    }
    __syncthreads();
    int i = blockIdx.x * 256 + t;
    if (i < NN) {
        int r = g_rowptr[i] + off;
        g_rowptr[i] = r;
        g_fill[i] = r;
    }
    if (i == 0) g_rowptr[NN] = E;
}

// ---------------- scatter into CSR (src + dst), 8 edges/thread ----------
__global__ void k_scatter(const void* __restrict__ raw, int E) {
    int base = (blockIdx.x * blockDim.x + threadIdx.x) * 8;
    if (g_flag) {
        const long long* p = (const long long*)raw;
#pragma unroll
        for (int u = 0; u < 8; u++) {
            int j = base + u;
            if (j < E) {
                int s = (int)p[j], d = (int)p[E + j];
                int pos = atomicAdd(&g_fill[d], 1);
                g_srcs16[pos] = (unsigned short)s;
                g_dst16[pos] = (unsigned short)d;
            }
        }
    } else {
        const int* p = (const int*)raw;
#pragma unroll
        for (int u = 0; u < 8; u++) {
            int j = base + u;
            if (j < E) {
                int s = p[j], d = p[E + j];
                int pos = atomicAdd(&g_fill[d], 1);
                g_srcs16[pos] = (unsigned short)s;
                g_dst16[pos] = (unsigned short)d;
            }
        }
    }
}

// ---------------- tensor-core GEMM (fp16 single MMA, static smem) -------
// h = x @ W. 256 threads; warp w: one m16 tile x 8 n8 tiles; fp32 accum.
__global__ void __launch_bounds__(256) k_gemm(
        int g, const float* __restrict__ a_s, const float* __restrict__ a_d) {
    __shared__ __align__(16) __half Ah[BR][72];   // 18432 B
    __shared__ __align__(16) __half Bh[DD][72];   //  9216 B
    int t = threadIdx.x;
    int rb = blockIdx.x * BR;

    for (int i = t; i < 512; i += 256) {
        int c = i >> 3, q = i & 7;
        ((uint4*)&Bh[c][0])[q] = ((const uint4*)(g_W + g * DD * DD + c * DD))[q];
    }
    for (int i = t; i < 1024; i += 256) {
        int r = i >> 3, q = i & 7;
        int gr = rb + r; if (gr >= NN) gr = 0;
        ((uint4*)&Ah[r][0])[q] = ((const uint4*)(g_x + (size_t)gr * DD))[q];
    }
    __syncthreads();

    int lane = t & 31, wid = t >> 5;
    int gid = lane >> 2, tig = lane & 3;

    float acc[8][4];
#pragma unroll
    for (int nt = 0; nt < 8; nt++)
#pragma unroll
        for (int q = 0; q < 4; q++) acc[nt][q] = 0.f;

#pragma unroll
    for (int ks = 0; ks < 4; ks++) {
        int k0 = ks * 16 + 2 * tig;
        int r0 = wid * 16 + gid;
        uint32_t a[4];
        a[0] = *(const uint32_t*)&Ah[r0][k0];
        a[1] = *(const uint32_t*)&Ah[r0 + 8][k0];
        a[2] = *(const uint32_t*)&Ah[r0][k0 + 8];
        a[3] = *(const uint32_t*)&Ah[r0 + 8][k0 + 8];
#pragma unroll
        for (int nt = 0; nt < 8; nt++) {
            int n = nt * 8 + gid;
            uint32_t b0 = *(const uint32_t*)&Bh[n][k0];
            uint32_t b1 = *(const uint32_t*)&Bh[n][k0 + 8];
            asm volatile(
                "mma.sync.aligned.m16n8k16.row.col.f32.f16.f16.f32 "
                "{%0,%1,%2,%3}, {%4,%5,%6,%7}, {%8,%9}, {%0,%1,%2,%3};"
                : "+f"(acc[nt][0]), "+f"(acc[nt][1]), "+f"(acc[nt][2]), "+f"(acc[nt][3])
                : "r"(a[0]), "r"(a[1]), "r"(a[2]), "r"(a[3]),
                  "r"(b0), "r"(b1));
        }
    }

    float2 asv[8], adv[8];
#pragma unroll
    for (int nt = 0; nt < 8; nt++) {
        asv[nt] = ((const float2*)a_s)[nt * 4 + tig];
        adv[nt] = ((const float2*)a_d)[nt * 4 + tig];
    }
    int r0 = rb + wid * 16 + gid;
    float ss0 = 0.f, sd0 = 0.f, ss1 = 0.f, sd1 = 0.f;
#pragma unroll
    for (int nt = 0; nt < 8; nt++) {
        ss0 = fmaf(acc[nt][0], asv[nt].x, fmaf(acc[nt][1], asv[nt].y, ss0));
        sd0 = fmaf(acc[nt][0], adv[nt].x, fmaf(acc[nt][1], adv[nt].y, sd0));
        ss1 = fmaf(acc[nt][2], asv[nt].x, fmaf(acc[nt][3], asv[nt].y, ss1));
        sd1 = fmaf(acc[nt][2], adv[nt].x, fmaf(acc[nt][3], adv[nt].y, sd1));
    }
#pragma unroll
    for (int o = 1; o <= 2; o <<= 1) {
        ss0 += __shfl_xor_sync(0xffffffffu, ss0, o);
        sd0 += __shfl_xor_sync(0xffffffffu, sd0, o);
        ss1 += __shfl_xor_sync(0xffffffffu, ss1, o);
        sd1 += __shfl_xor_sync(0xffffffffu, sd1, o);
    }
    bool ok0 = (r0 < NN), ok1 = (r0 + 8 < NN);
#pragma unroll
    for (int nt = 0; nt < 8; nt++) {
        int col = nt * 8 + 2 * tig;
        if (ok0)
            *(__half2*)(g_hh + (size_t)r0 * DD + col) =
                __floats2half2_rn(acc[nt][0], acc[nt][1]);
        if (ok1)
            *(__half2*)(g_hh + (size_t)(r0 + 8) * DD + col) =
                __floats2half2_rn(acc[nt][2], acc[nt][3]);
    }
    if (tig == 0) {
        if (ok0) { g_ssrc[r0] = ss0; g_sdst[r0] = sd0; g_z[r0] = 0.f; }
        if (ok1) { g_ssrc[r0 + 8] = ss1; g_sdst[r0 + 8] = sd1; g_z[r0 + 8] = 0.f; }
    }
}

// ---------------- aggA: edge-parallel exp + z reduction (REDG) ----------
__global__ void k_aggA(int E) {
    int base = (blockIdx.x * blockDim.x + threadIdx.x) * 4;
#pragma unroll
    for (int u = 0; u < 4; u++) {
        int j = base + u;
        if (j < E) {
            int s = g_srcs16[j];
            int d = g_dst16[j];
            float e = g_ssrc[s] + g_sdst[d];
            e = (e > 0.f) ? e : 0.2f * e;
            float p = __expf(fminf(e, 60.f));
            g_pe[j] = p;
            atomicAdd(&g_z[d], p);     // no return value -> REDG
        }
    }
}

// ---------------- aggB: node-parallel weighted gather --------------------
__global__ void __launch_bounds__(256) k_aggB(float* __restrict__ yext,
                                              int is_last, int do_elu) {
    int w = (blockIdx.x * blockDim.x + threadIdx.x) >> 5;
    int lane = threadIdx.x & 31;
    if (w >= NN) return;
    int start = g_rowptr[w], end = g_rowptr[w + 1];
    float inv = 1.f / (g_z[w] + 1e-16f);

    int q = lane >> 3, l8 = lane & 7;
    float acc[8];
#pragma unroll
    for (int i = 0; i < 8; i++) acc[i] = 0.f;
    const uint4* h16 = (const uint4*)g_hh;
#pragma unroll 4
    for (int j = start + q; j < end; j += 4) {
        int s = g_srcs16[j];
        float p = g_pe[j];
        uint4 hv = h16[(size_t)s * 8 + l8];
        float2 f0 = __half22float2(*reinterpret_cast<const __half2*>(&hv.x));
        float2 f1 = __half22float2(*reinterpret_cast<const __half2*>(&hv.y));
        float2 f2 = __half22float2(*reinterpret_cast<const __half2*>(&hv.z));
        float2 f3 = __half22float2(*reinterpret_cast<const __half2*>(&hv.w));
        acc[0] = fmaf(f0.x, p, acc[0]);
        acc[1] = fmaf(f0.y, p, acc[1]);
        acc[2] = fmaf(f1.x, p, acc[2]);
        acc[3] = fmaf(f1.y, p, acc[3]);
        acc[4] = fmaf(f2.x, p, acc[4]);
        acc[5] = fmaf(f2.y, p, acc[5]);
        acc[6] = fmaf(f3.x, p, acc[6]);
        acc[7] = fmaf(f3.y, p, acc[7]);
    }
#pragma unroll
    for (int i = 0; i < 8; i++) {
        acc[i] += __shfl_xor_sync(0xffffffffu, acc[i], 8);
        acc[i] += __shfl_xor_sync(0xffffffffu, acc[i], 16);
    }
    if (q == 0) {
#pragma unroll
        for (int i = 0; i < 8; i++) acc[i] *= inv;
        if (do_elu) {
#pragma unroll
            for (int i = 0; i < 8; i++)
                acc[i] = (acc[i] > 0.f) ? acc[i] : (__expf(acc[i]) - 1.f);
        }
        if (is_last) {
            float4 v0 = make_float4(acc[0], acc[1], acc[2], acc[3]);
            float4 v1 = make_float4(acc[4], acc[5], acc[6], acc[7]);
            ((float4*)yext)[(size_t)w * 16 + l8 * 2]     = v0;
            ((float4*)yext)[(size_t)w * 16 + l8 * 2 + 1] = v1;
        } else {
            uint4 pk;
            *reinterpret_cast<__half2*>(&pk.x) = __floats2half2_rn(acc[0], acc[1]);
            *reinterpret_cast<__half2*>(&pk.y) = __floats2half2_rn(acc[2], acc[3]);
            *reinterpret_cast<__half2*>(&pk.z) = __floats2half2_rn(acc[4], acc[5]);
            *reinterpret_cast<__half2*>(&pk.w) = __floats2half2_rn(acc[6], acc[7]);
            *(uint4*)(g_x + (size_t)w * DD + l8 * 8) = pk;
        }
    }
}

// ---------------- launch ----------------
extern "C" void kernel_launch(void* const* d_in, const int* in_sizes, int n_in,
                              void* d_out, int out_size) {
    const float* feat  = (const float*)d_in[0];
    const void*  eidx  = d_in[1];
    const float* W1    = (const float*)d_in[2];
    const float* a_s1  = (const float*)d_in[3];
    const float* a_d1  = (const float*)d_in[4];
    const float* W2    = (const float*)d_in[5];
    const float* a_s2  = (const float*)d_in[6];
    const float* a_d2  = (const float*)d_in[7];
    float* out = (float*)d_out;

    int E = in_sizes[1] / 2;

    static int init_done = 0;
    static cudaStream_t s_side;
    static cudaEvent_t ev_fork, ev_join;
    if (!init_done) {
        cudaStreamCreateWithFlags(&s_side, cudaStreamNonBlocking);
        cudaEventCreateWithFlags(&ev_fork, cudaEventDisableTiming);
        cudaEventCreateWithFlags(&ev_join, cudaEventDisableTiming);
        init_done = 1;
    }

    const int gemm_grid = (NN + BR - 1) / BR;
    const int aggB_grid = (NN * 32 + 255) / 256;
    const int e4_grid   = (E / 4 + 255) / 256;
    const int e8_grid   = (E / 8 + 255) / 256;

    // init0 (zero cnt + dtype flag) on main, then fork CSR chain to side.
    k_init0<<<(NN + 255) / 256, 256>>>((const int*)eidx);
    cudaEventRecord(ev_fork, 0);
    cudaStreamWaitEvent(s_side, ev_fork, 0);

    // side stream: CSR build (independent of cvt/gemm)
    k_hist<<<e8_grid, 256, 0, s_side>>>(eidx, E);
    k_scanA<<<NB, 256, 0, s_side>>>();
    k_scanC<<<NB, 256, 0, s_side>>>(E);
    k_scatter<<<e8_grid, 256, 0, s_side>>>(eidx, E);
    cudaEventRecord(ev_join, s_side);

    // main stream: cvt + gemm head 0 (overlaps with CSR build)
    k_cvt<<<(NN * DD + 255) / 256, 256>>>(feat, W1, W2);
    k_gemm<<<gemm_grid, 256>>>(0, a_s1, a_d1);

    // join: aggA needs both CSR (side) and gemm0 (main)
    cudaStreamWaitEvent(0, ev_join, 0);
    k_aggA<<<e4_grid, 256>>>(E);
    k_aggB<<<aggB_grid, 256>>>(out, 0, 0);

    for (int layer = 0; layer < 2; layer++) {
        const float* as = layer ? a_s2 : a_s1;
        const float* ad = layer ? a_d2 : a_d1;
        for (int head = (layer == 0 ? 1 : 0); head < 4; head++) {
            int g = layer * 4 + head;
            int last = (layer == 1 && head == 3);
            int eol  = (head == 3);
            k_gemm<<<gemm_grid, 256>>>(g, as + head * DD, ad + head * DD);
            k_aggA<<<e4_grid, 256>>>(E);
            k_aggB<<<aggB_grid, 256>>>(out, last, eol);
        }
    }
}

// round 15
// speedup vs baseline: 1.7057x; 1.0566x over previous
#include <cuda_runtime.h>
#include <cuda_fp16.h>
#include <stdint.h>

#define NN 50000
#define EE 800000
#define DD 64
#define BR 128   // rows per GEMM block (8 warps x 16 rows)
#define NB ((NN + 255) / 256)   // 196 scan blocks

// ---------------- device scratch (static, no allocation) ----------------
__device__ int   g_flag;
__device__ int   g_cnt[NN];
__device__ int   g_rowptr[NN + 1];
__device__ int   g_fill[NN];
__device__ int   g_bsum[NB];
__device__ unsigned short g_srcs16[EE];
__device__ __align__(16) __half g_x[NN * DD];           // layer input (fp16)
__device__ __align__(16) __half g_W[8 * DD * DD];       // W^T (fp16), 8 slots
__device__ __align__(16) __half g_hh[NN * DD];          // per-conv h (fp16)
__device__ float g_ssrc[NN];
__device__ float g_sdst[NN];

// ---------------- init0: zero counters + dtype detect (tiny) ------------
__global__ void k_init0(const int* __restrict__ raw) {
    int i = blockIdx.x * blockDim.x + threadIdx.x;
    if (i < NN) g_cnt[i] = 0;
    if (blockIdx.x == 0) {
        __shared__ int ok;
        if (threadIdx.x == 0) ok = 1;
        __syncthreads();
        for (int j = threadIdx.x; j < 4096; j += blockDim.x)
            if (raw[2 * j + 1] != 0) ok = 0;
        __syncthreads();
        if (threadIdx.x == 0) g_flag = ok;
    }
}

// ---------------- cvt: feat + W -> fp16 (W transposed) -------------------
__global__ void k_cvt(const float* __restrict__ feat,
                      const float* __restrict__ W1,
                      const float* __restrict__ W2) {
    int i = blockIdx.x * blockDim.x + threadIdx.x;
    if (i < NN * DD) g_x[i] = __float2half_rn(feat[i]);
    if (i < 8 * DD * DD) {
        int g = i >> 12;
        int idx = i & 4095;
        int k = idx >> 6, c = idx & 63;
        const float* W = (g < 4) ? W1 : W2;
        g_W[g * DD * DD + c * DD + k] =
            __float2half_rn(W[(g & 3) * DD * DD + k * DD + c]);
    }
}

// ---------------- histogram of dst, 8 edges/thread ----------------------
__global__ void k_hist(const void* __restrict__ raw, int E) {
    int base = (blockIdx.x * blockDim.x + threadIdx.x) * 8;
    if (g_flag) {
        const long long* p = (const long long*)raw + E;
#pragma unroll
        for (int u = 0; u < 8; u++) { int j = base + u; if (j < E) atomicAdd(&g_cnt[(int)p[j]], 1); }
    } else {
        const int* p = (const int*)raw + E;
#pragma unroll
        for (int u = 0; u < 8; u++) { int j = base + u; if (j < E) atomicAdd(&g_cnt[p[j]], 1); }
    }
}

// ---------------- 2-phase parallel scan ----------------
__global__ void k_scanA() {
    __shared__ int sh[256];
    int t = threadIdx.x;
    int i = blockIdx.x * 256 + t;
    int v = (i < NN) ? g_cnt[i] : 0;
    sh[t] = v;
    __syncthreads();
#pragma unroll
    for (int off = 1; off < 256; off <<= 1) {
        int u = (t >= off) ? sh[t - off] : 0;
        __syncthreads();
        sh[t] += u;
        __syncthreads();
    }
    if (i < NN) g_rowptr[i] = sh[t] - v;
    if (t == 255) g_bsum[blockIdx.x] = sh[255];
}

__global__ void k_scanC(int E) {
    __shared__ int wsum[8];
    __shared__ int off;
    int t = threadIdx.x;
    int partial = 0;
    for (int j = t; j < blockIdx.x; j += 256) partial += g_bsum[j];
#pragma unroll
    for (int o = 16; o; o >>= 1) partial += __shfl_xor_sync(0xffffffffu, partial, o);
    if ((t & 31) == 0) wsum[t >> 5] = partial;
    __syncthreads();
    if (t == 0) {
        int s = 0;
#pragma unroll
        for (int i = 0; i < 8; i++) s += wsum[i];
        off = s;
    }
    __syncthreads();
    int i = blockIdx.x * 256 + t;
    if (i < NN) {
        int r = g_rowptr[i] + off;
        g_rowptr[i] = r;
        g_fill[i] = r;
    }
    if (i == 0) g_rowptr[NN] = E;
}

// ---------------- scatter into CSR (src only), 8 edges/thread -----------
__global__ void k_scatter(const void* __restrict__ raw, int E) {
    int base = (blockIdx.x * blockDim.x + threadIdx.x) * 8;
    if (g_flag) {
        const long long* p = (const long long*)raw;
#pragma unroll
        for (int u = 0; u < 8; u++) {
            int j = base + u;
            if (j < E) {
                int s = (int)p[j], d = (int)p[E + j];
                int pos = atomicAdd(&g_fill[d], 1);
                g_srcs16[pos] = (unsigned short)s;
            }
        }
    } else {
        const int* p = (const int*)raw;
#pragma unroll
        for (int u = 0; u < 8; u++) {
            int j = base + u;
            if (j < E) {
                int s = p[j], d = p[E + j];
                int pos = atomicAdd(&g_fill[d], 1);
                g_srcs16[pos] = (unsigned short)s;
            }
        }
    }
}

// ---------------- tensor-core GEMM (fp16 single MMA, static smem) -------
__global__ void __launch_bounds__(256) k_gemm(
        int g, const float* __restrict__ a_s, const float* __restrict__ a_d) {
    __shared__ __align__(16) __half Ah[BR][72];   // 18432 B
    __shared__ __align__(16) __half Bh[DD][72];   //  9216 B
    int t = threadIdx.x;
    int rb = blockIdx.x * BR;

    for (int i = t; i < 512; i += 256) {
        int c = i >> 3, q = i & 7;
        ((uint4*)&Bh[c][0])[q] = ((const uint4*)(g_W + g * DD * DD + c * DD))[q];
    }
    for (int i = t; i < 1024; i += 256) {
        int r = i >> 3, q = i & 7;
        int gr = rb + r; if (gr >= NN) gr = 0;
        ((uint4*)&Ah[r][0])[q] = ((const uint4*)(g_x + (size_t)gr * DD))[q];
    }
    __syncthreads();

    int lane = t & 31, wid = t >> 5;
    int gid = lane >> 2, tig = lane & 3;

    float acc[8][4];
#pragma unroll
    for (int nt = 0; nt < 8; nt++)
#pragma unroll
        for (int q = 0; q < 4; q++) acc[nt][q] = 0.f;

#pragma unroll
    for (int ks = 0; ks < 4; ks++) {
        int k0 = ks * 16 + 2 * tig;
        int r0 = wid * 16 + gid;
        uint32_t a[4];
        a[0] = *(const uint32_t*)&Ah[r0][k0];
        a[1] = *(const uint32_t*)&Ah[r0 + 8][k0];
        a[2] = *(const uint32_t*)&Ah[r0][k0 + 8];
        a[3] = *(const uint32_t*)&Ah[r0 + 8][k0 + 8];
#pragma unroll
        for (int nt = 0; nt < 8; nt++) {
            int n = nt * 8 + gid;
            uint32_t b0 = *(const uint32_t*)&Bh[n][k0];
            uint32_t b1 = *(const uint32_t*)&Bh[n][k0 + 8];
            asm volatile(
                "mma.sync.aligned.m16n8k16.row.col.f32.f16.f16.f32 "
                "{%0,%1,%2,%3}, {%4,%5,%6,%7}, {%8,%9}, {%0,%1,%2,%3};"
                : "+f"(acc[nt][0]), "+f"(acc[nt][1]), "+f"(acc[nt][2]), "+f"(acc[nt][3])
                : "r"(a[0]), "r"(a[1]), "r"(a[2]), "r"(a[3]),
                  "r"(b0), "r"(b1));
        }
    }

    float2 asv[8], adv[8];
#pragma unroll
    for (int nt = 0; nt < 8; nt++) {
        asv[nt] = ((const float2*)a_s)[nt * 4 + tig];
        adv[nt] = ((const float2*)a_d)[nt * 4 + tig];
    }
    int r0 = rb + wid * 16 + gid;
    float ss0 = 0.f, sd0 = 0.f, ss1 = 0.f, sd1 = 0.f;
#pragma unroll
    for (int nt = 0; nt < 8; nt++) {
        ss0 = fmaf(acc[nt][0], asv[nt].x, fmaf(acc[nt][1], asv[nt].y, ss0));
        sd0 = fmaf(acc[nt][0], adv[nt].x, fmaf(acc[nt][1], adv[nt].y, sd0));
        ss1 = fmaf(acc[nt][2], asv[nt].x, fmaf(acc[nt][3], asv[nt].y, ss1));
        sd1 = fmaf(acc[nt][2], adv[nt].x, fmaf(acc[nt][3], adv[nt].y, sd1));
    }
#pragma unroll
    for (int o = 1; o <= 2; o <<= 1) {
        ss0 += __shfl_xor_sync(0xffffffffu, ss0, o);
        sd0 += __shfl_xor_sync(0xffffffffu, sd0, o);
        ss1 += __shfl_xor_sync(0xffffffffu, ss1, o);
        sd1 += __shfl_xor_sync(0xffffffffu, sd1, o);
    }
    bool ok0 = (r0 < NN), ok1 = (r0 + 8 < NN);
#pragma unroll
    for (int nt = 0; nt < 8; nt++) {
        int col = nt * 8 + 2 * tig;
        if (ok0)
            *(__half2*)(g_hh + (size_t)r0 * DD + col) =
                __floats2half2_rn(acc[nt][0], acc[nt][1]);
        if (ok1)
            *(__half2*)(g_hh + (size_t)(r0 + 8) * DD + col) =
                __floats2half2_rn(acc[nt][2], acc[nt][3]);
    }
    if (tig == 0) {
        if (ok0) { g_ssrc[r0] = ss0; g_sdst[r0] = sd0; }
        if (ok1) { g_ssrc[r0 + 8] = ss1; g_sdst[r0 + 8] = sd1; }
    }
}

// ---------------- fused agg: softmax + weighted gather -------------------
// One warp per dst node. Per iteration (4 edges): lanes 0-3 compute
// p = exp(leaky(e)) for one edge each (1 exp/edge total), shuffles broadcast
// (p, s) to quarter-warps, which gather h (uint4 = 8 fp16 per lane).
// z accumulates alongside; 1/z applied after the loop (softmax deferred).
__global__ void __launch_bounds__(256) k_agg(float* __restrict__ yext,
                                             int is_last, int do_elu) {
    int w = (blockIdx.x * blockDim.x + threadIdx.x) >> 5;
    int lane = threadIdx.x & 31;
    if (w >= NN) return;
    int start = g_rowptr[w], end = g_rowptr[w + 1];
    float sd = g_sdst[w];

    int q = lane >> 3, l8 = lane & 7;
    float acc[8];
#pragma unroll
    for (int i = 0; i < 8; i++) acc[i] = 0.f;
    float z = 0.f;
    const uint4* h16 = (const uint4*)g_hh;

    for (int j0 = start; j0 < end; j0 += 4) {
        // lanes 0-3: per-edge score -> p
        float p = 0.f; int s = 0;
        if (lane < 4) {
            int j = j0 + lane;
            if (j < end) {
                s = g_srcs16[j];
                float e = g_ssrc[s] + sd;
                e = (e > 0.f) ? e : 0.2f * e;
                p = __expf(fminf(e, 60.f));
            }
        }
        float pq = __shfl_sync(0xffffffffu, p, q);
        int   sq = __shfl_sync(0xffffffffu, s, q);
        z += pq;                      // per-quarter sum (replicated in 8 lanes)
        if (j0 + q < end) {
            uint4 hv = h16[(size_t)sq * 8 + l8];
            float2 f0 = __half22float2(*reinterpret_cast<const __half2*>(&hv.x));
            float2 f1 = __half22float2(*reinterpret_cast<const __half2*>(&hv.y));
            float2 f2 = __half22float2(*reinterpret_cast<const __half2*>(&hv.z));
            float2 f3 = __half22float2(*reinterpret_cast<const __half2*>(&hv.w));
            acc[0] = fmaf(f0.x, pq, acc[0]);
            acc[1] = fmaf(f0.y, pq, acc[1]);
            acc[2] = fmaf(f1.x, pq, acc[2]);
            acc[3] = fmaf(f1.y, pq, acc[3]);
            acc[4] = fmaf(f2.x, pq, acc[4]);
            acc[5] = fmaf(f2.y, pq, acc[5]);
            acc[6] = fmaf(f3.x, pq, acc[6]);
            acc[7] = fmaf(f3.y, pq, acc[7]);
        }
    }
    // reduce acc and z over quarter-warps
#pragma unroll
    for (int i = 0; i < 8; i++) {
        acc[i] += __shfl_xor_sync(0xffffffffu, acc[i], 8);
        acc[i] += __shfl_xor_sync(0xffffffffu, acc[i], 16);
    }
    z += __shfl_xor_sync(0xffffffffu, z, 8);
    z += __shfl_xor_sync(0xffffffffu, z, 16);

    if (q == 0) {
        float inv = 1.f / (z + 1e-16f);
#pragma unroll
        for (int i = 0; i < 8; i++) acc[i] *= inv;
        if (do_elu) {
#pragma unroll
            for (int i = 0; i < 8; i++)
                acc[i] = (acc[i] > 0.f) ? acc[i] : (__expf(acc[i]) - 1.f);
        }
        if (is_last) {
            float4 v0 = make_float4(acc[0], acc[1], acc[2], acc[3]);
            float4 v1 = make_float4(acc[4], acc[5], acc[6], acc[7]);
            ((float4*)yext)[(size_t)w * 16 + l8 * 2]     = v0;
            ((float4*)yext)[(size_t)w * 16 + l8 * 2 + 1] = v1;
        } else {
            uint4 pk;
            *reinterpret_cast<__half2*>(&pk.x) = __floats2half2_rn(acc[0], acc[1]);
            *reinterpret_cast<__half2*>(&pk.y) = __floats2half2_rn(acc[2], acc[3]);
            *reinterpret_cast<__half2*>(&pk.z) = __floats2half2_rn(acc[4], acc[5]);
            *reinterpret_cast<__half2*>(&pk.w) = __floats2half2_rn(acc[6], acc[7]);
            *(uint4*)(g_x + (size_t)w * DD + l8 * 8) = pk;
        }
    }
}

// ---------------- launch ----------------
extern "C" void kernel_launch(void* const* d_in, const int* in_sizes, int n_in,
                              void* d_out, int out_size) {
    const float* feat  = (const float*)d_in[0];
    const void*  eidx  = d_in[1];
    const float* W1    = (const float*)d_in[2];
    const float* a_s1  = (const float*)d_in[3];
    const float* a_d1  = (const float*)d_in[4];
    const float* W2    = (const float*)d_in[5];
    const float* a_s2  = (const float*)d_in[6];
    const float* a_d2  = (const float*)d_in[7];
    float* out = (float*)d_out;

    int E = in_sizes[1] / 2;

    static int init_done = 0;
    static cudaStream_t s_side;
    static cudaEvent_t ev_fork, ev_join;
    if (!init_done) {
        cudaStreamCreateWithFlags(&s_side, cudaStreamNonBlocking);
        cudaEventCreateWithFlags(&ev_fork, cudaEventDisableTiming);
        cudaEventCreateWithFlags(&ev_join, cudaEventDisableTiming);
        init_done = 1;
    }

    const int gemm_grid = (NN + BR - 1) / BR;
    const int agg_grid  = (NN * 32 + 255) / 256;
    const int e8_grid   = (E / 8 + 255) / 256;

    // init0 (zero cnt + dtype flag) on main, then fork CSR chain to side.
    k_init0<<<(NN + 255) / 256, 256>>>((const int*)eidx);
    cudaEventRecord(ev_fork, 0);
    cudaStreamWaitEvent(s_side, ev_fork, 0);

    // side stream: CSR build (independent of cvt/gemm)
    k_hist<<<e8_grid, 256, 0, s_side>>>(eidx, E);
    k_scanA<<<NB, 256, 0, s_side>>>();
    k_scanC<<<NB, 256, 0, s_side>>>(E);
    k_scatter<<<e8_grid, 256, 0, s_side>>>(eidx, E);
    cudaEventRecord(ev_join, s_side);

    // main stream: cvt + gemm head 0 (overlaps with CSR build)
    k_cvt<<<(NN * DD + 255) / 256, 256>>>(feat, W1, W2);
    k_gemm<<<gemm_grid, 256>>>(0, a_s1, a_d1);

    // join: agg needs both CSR (side) and gemm0 (main)
    cudaStreamWaitEvent(0, ev_join, 0);
    k_agg<<<agg_grid, 256>>>(out, 0, 0);

    for (int layer = 0; layer < 2; layer++) {
        const float* as = layer ? a_s2 : a_s1;
        const float* ad = layer ? a_d2 : a_d1;
        for (int head = (layer == 0 ? 1 : 0); head < 4; head++) {
            int g = layer * 4 + head;
            int last = (layer == 1 && head == 3);
            int eol  = (head == 3);
            k_gemm<<<gemm_grid, 256>>>(g, as + head * DD, ad + head * DD);
            k_agg<<<agg_grid, 256>>>(out, last, eol);
        }
    }
}

// round 16
// speedup vs baseline: 1.7059x; 1.0001x over previous
#include <cuda_runtime.h>
#include <cuda_fp16.h>
#include <stdint.h>

#define NN 50000
#define EE 800000
#define DD 64
#define BR 128   // rows per GEMM block (8 warps x 16 rows)
#define NB ((NN + 255) / 256)   // 196 scan blocks

// ---------------- device scratch (static, no allocation) ----------------
__device__ int   g_flag;
__device__ int   g_cnt[NN];
__device__ int   g_rowptr[NN + 1];
__device__ int   g_fill[NN];
__device__ int   g_bsum[NB];
__device__ unsigned short g_srcs16[EE];
__device__ __align__(16) __half g_x[NN * DD];           // layer input (fp16)
__device__ __align__(16) __half g_W[8 * DD * DD];       // W^T (fp16), 8 slots
__device__ __align__(16) __half g_hh[NN * DD];          // per-conv h (fp16)
__device__ float g_ssrc[NN];
__device__ float g_sdst[NN];

// ---------------- init0: zero counters + dtype detect (tiny) ------------
__global__ void k_init0(const int* __restrict__ raw) {
    int i = blockIdx.x * blockDim.x + threadIdx.x;
    if (i < NN) g_cnt[i] = 0;
    if (blockIdx.x == 0) {
        __shared__ int ok;
        if (threadIdx.x == 0) ok = 1;
        __syncthreads();
        for (int j = threadIdx.x; j < 4096; j += blockDim.x)
            if (raw[2 * j + 1] != 0) ok = 0;
        __syncthreads();
        if (threadIdx.x == 0) g_flag = ok;
    }
}

// ---------------- cvt: feat + W -> fp16 (W transposed) -------------------
__global__ void k_cvt(const float* __restrict__ feat,
                      const float* __restrict__ W1,
                      const float* __restrict__ W2) {
    int i = blockIdx.x * blockDim.x + threadIdx.x;
    if (i < NN * DD) g_x[i] = __float2half_rn(feat[i]);
    if (i < 8 * DD * DD) {
        int g = i >> 12;
        int idx = i & 4095;
        int k = idx >> 6, c = idx & 63;
        const float* W = (g < 4) ? W1 : W2;
        g_W[g * DD * DD + c * DD + k] =
            __float2half_rn(W[(g & 3) * DD * DD + k * DD + c]);
    }
}

// ---------------- histogram of dst, 8 edges/thread ----------------------
__global__ void k_hist(const void* __restrict__ raw, int E) {
    int base = (blockIdx.x * blockDim.x + threadIdx.x) * 8;
    if (g_flag) {
        const long long* p = (const long long*)raw + E;
#pragma unroll
        for (int u = 0; u < 8; u++) { int j = base + u; if (j < E) atomicAdd(&g_cnt[(int)p[j]], 1); }
    } else {
        const int* p = (const int*)raw + E;
#pragma unroll
        for (int u = 0; u < 8; u++) { int j = base + u; if (j < E) atomicAdd(&g_cnt[p[j]], 1); }
    }
}

// ---------------- 2-phase parallel scan ----------------
__global__ void k_scanA() {
    __shared__ int sh[256];
    int t = threadIdx.x;
    int i = blockIdx.x * 256 + t;
    int v = (i < NN) ? g_cnt[i] : 0;
    sh[t] = v;
    __syncthreads();
#pragma unroll
    for (int off = 1; off < 256; off <<= 1) {
        int u = (t >= off) ? sh[t - off] : 0;
        __syncthreads();
        sh[t] += u;
        __syncthreads();
    }
    if (i < NN) g_rowptr[i] = sh[t] - v;
    if (t == 255) g_bsum[blockIdx.x] = sh[255];
}

__global__ void k_scanC(int E) {
    __shared__ int wsum[8];
    __shared__ int off;
    int t = threadIdx.x;
    int partial = 0;
    for (int j = t; j < blockIdx.x; j += 256) partial += g_bsum[j];
#pragma unroll
    for (int o = 16; o; o >>= 1) partial += __shfl_xor_sync(0xffffffffu, partial, o);
    if ((t & 31) == 0) wsum[t >> 5] = partial;
    __syncthreads();
    if (t == 0) {
        int s = 0;
#pragma unroll
        for (int i = 0; i < 8; i++) s += wsum[i];
        off = s;
    }
    __syncthreads();
    int i = blockIdx.x * 256 + t;
    if (i < NN) {
        int r = g_rowptr[i] + off;
        g_rowptr[i] = r;
        g_fill[i] = r;
    }
    if (i == 0) g_rowptr[NN] = E;
}

// ---------------- scatter into CSR (src only), 8 edges/thread -----------
__global__ void k_scatter(const void* __restrict__ raw, int E) {
    int base = (blockIdx.x * blockDim.x + threadIdx.x) * 8;
    if (g_flag) {
        const long long* p = (const long long*)raw;
#pragma unroll
        for (int u = 0; u < 8; u++) {
            int j = base + u;
            if (j < E) {
                int s = (int)p[j], d = (int)p[E + j];
                int pos = atomicAdd(&g_fill[d], 1);
                g_srcs16[pos] = (unsigned short)s;
            }
        }
    } else {
        const int* p = (const int*)raw;
#pragma unroll
        for (int u = 0; u < 8; u++) {
            int j = base + u;
            if (j < E) {
                int s = p[j], d = p[E + j];
                int pos = atomicAdd(&g_fill[d], 1);
                g_srcs16[pos] = (unsigned short)s;
            }
        }
    }
}

// ---------------- tensor-core GEMM (fp16 single MMA, static smem) -------
__global__ void __launch_bounds__(256) k_gemm(
        int g, const float* __restrict__ a_s, const float* __restrict__ a_d) {
    __shared__ __align__(16) __half Ah[BR][72];   // 18432 B
    __shared__ __align__(16) __half Bh[DD][72];   //  9216 B
    int t = threadIdx.x;
    int rb = blockIdx.x * BR;

    for (int i = t; i < 512; i += 256) {
        int c = i >> 3, q = i & 7;
        ((uint4*)&Bh[c][0])[q] = ((const uint4*)(g_W + g * DD * DD + c * DD))[q];
    }
    for (int i = t; i < 1024; i += 256) {
        int r = i >> 3, q = i & 7;
        int gr = rb + r; if (gr >= NN) gr = 0;
        ((uint4*)&Ah[r][0])[q] = ((const uint4*)(g_x + (size_t)gr * DD))[q];
    }
    __syncthreads();

    int lane = t & 31, wid = t >> 5;
    int gid = lane >> 2, tig = lane & 3;

    float acc[8][4];
#pragma unroll
    for (int nt = 0; nt < 8; nt++)
#pragma unroll
        for (int q = 0; q < 4; q++) acc[nt][q] = 0.f;

#pragma unroll
    for (int ks = 0; ks < 4; ks++) {
        int k0 = ks * 16 + 2 * tig;
        int r0 = wid * 16 + gid;
        uint32_t a[4];
        a[0] = *(const uint32_t*)&Ah[r0][k0];
        a[1] = *(const uint32_t*)&Ah[r0 + 8][k0];
        a[2] = *(const uint32_t*)&Ah[r0][k0 + 8];
        a[3] = *(const uint32_t*)&Ah[r0 + 8][k0 + 8];
#pragma unroll
        for (int nt = 0; nt < 8; nt++) {
            int n = nt * 8 + gid;
            uint32_t b0 = *(const uint32_t*)&Bh[n][k0];
            uint32_t b1 = *(const uint32_t*)&Bh[n][k0 + 8];
            asm volatile(
                "mma.sync.aligned.m16n8k16.row.col.f32.f16.f16.f32 "
                "{%0,%1,%2,%3}, {%4,%5,%6,%7}, {%8,%9}, {%0,%1,%2,%3};"
                : "+f"(acc[nt][0]), "+f"(acc[nt][1]), "+f"(acc[nt][2]), "+f"(acc[nt][3])
                : "r"(a[0]), "r"(a[1]), "r"(a[2]), "r"(a[3]),
                  "r"(b0), "r"(b1));
        }
    }

    float2 asv[8], adv[8];
#pragma unroll
    for (int nt = 0; nt < 8; nt++) {
        asv[nt] = ((const float2*)a_s)[nt * 4 + tig];
        adv[nt] = ((const float2*)a_d)[nt * 4 + tig];
    }
    int r0 = rb + wid * 16 + gid;
    float ss0 = 0.f, sd0 = 0.f, ss1 = 0.f, sd1 = 0.f;
#pragma unroll
    for (int nt = 0; nt < 8; nt++) {
        ss0 = fmaf(acc[nt][0], asv[nt].x, fmaf(acc[nt][1], asv[nt].y, ss0));
        sd0 = fmaf(acc[nt][0], adv[nt].x, fmaf(acc[nt][1], adv[nt].y, sd0));
        ss1 = fmaf(acc[nt][2], asv[nt].x, fmaf(acc[nt][3], asv[nt].y, ss1));
        sd1 = fmaf(acc[nt][2], adv[nt].x, fmaf(acc[nt][3], adv[nt].y, sd1));
    }
#pragma unroll
    for (int o = 1; o <= 2; o <<= 1) {
        ss0 += __shfl_xor_sync(0xffffffffu, ss0, o);
        sd0 += __shfl_xor_sync(0xffffffffu, sd0, o);
        ss1 += __shfl_xor_sync(0xffffffffu, ss1, o);
        sd1 += __shfl_xor_sync(0xffffffffu, sd1, o);
    }
    bool ok0 = (r0 < NN), ok1 = (r0 + 8 < NN);
#pragma unroll
    for (int nt = 0; nt < 8; nt++) {
        int col = nt * 8 + 2 * tig;
        if (ok0)
            *(__half2*)(g_hh + (size_t)r0 * DD + col) =
                __floats2half2_rn(acc[nt][0], acc[nt][1]);
        if (ok1)
            *(__half2*)(g_hh + (size_t)(r0 + 8) * DD + col) =
                __floats2half2_rn(acc[nt][2], acc[nt][3]);
    }
    if (tig == 0) {
        if (ok0) { g_ssrc[r0] = ss0; g_sdst[r0] = sd0; }
        if (ok1) { g_ssrc[r0 + 8] = ss1; g_sdst[r0 + 8] = sd1; }
    }
}

// ---------------- fused agg: softmax + weighted gather -------------------
// One warp per dst node. Per iteration (4 edges): lanes 0-3 compute
// p = exp(leaky(e)) for one edge each (1 exp/edge total), shuffles broadcast
// (p, s) to quarter-warps, which gather h (uint4 = 8 fp16 per lane).
// z accumulates alongside; 1/z applied after the loop (softmax deferred).
__global__ void __launch_bounds__(256) k_agg(float* __restrict__ yext,
                                             int is_last, int do_elu) {
    int w = (blockIdx.x * blockDim.x + threadIdx.x) >> 5;
    int lane = threadIdx.x & 31;
    if (w >= NN) return;
    int start = g_rowptr[w], end = g_rowptr[w + 1];
    float sd = g_sdst[w];

    int q = lane >> 3, l8 = lane & 7;
    float acc[8];
#pragma unroll
    for (int i = 0; i < 8; i++) acc[i] = 0.f;
    float z = 0.f;
    const uint4* h16 = (const uint4*)g_hh;

    for (int j0 = start; j0 < end; j0 += 4) {
        // lanes 0-3: per-edge score -> p
        float p = 0.f; int s = 0;
        if (lane < 4) {
            int j = j0 + lane;
            if (j < end) {
                s = g_srcs16[j];
                float e = g_ssrc[s] + sd;
                e = (e > 0.f) ? e : 0.2f * e;
                p = __expf(fminf(e, 60.f));
            }
        }
        float pq = __shfl_sync(0xffffffffu, p, q);
        int   sq = __shfl_sync(0xffffffffu, s, q);
        z += pq;                      // per-quarter sum (replicated in 8 lanes)
        if (j0 + q < end) {
            uint4 hv = h16[(size_t)sq * 8 + l8];
            float2 f0 = __half22float2(*reinterpret_cast<const __half2*>(&hv.x));
            float2 f1 = __half22float2(*reinterpret_cast<const __half2*>(&hv.y));
            float2 f2 = __half22float2(*reinterpret_cast<const __half2*>(&hv.z));
            float2 f3 = __half22float2(*reinterpret_cast<const __half2*>(&hv.w));
            acc[0] = fmaf(f0.x, pq, acc[0]);
            acc[1] = fmaf(f0.y, pq, acc[1]);
            acc[2] = fmaf(f1.x, pq, acc[2]);
            acc[3] = fmaf(f1.y, pq, acc[3]);
            acc[4] = fmaf(f2.x, pq, acc[4]);
            acc[5] = fmaf(f2.y, pq, acc[5]);
            acc[6] = fmaf(f3.x, pq, acc[6]);
            acc[7] = fmaf(f3.y, pq, acc[7]);
        }
    }
    // reduce acc and z over quarter-warps
#pragma unroll
    for (int i = 0; i < 8; i++) {
        acc[i] += __shfl_xor_sync(0xffffffffu, acc[i], 8);
        acc[i] += __shfl_xor_sync(0xffffffffu, acc[i], 16);
    }
    z += __shfl_xor_sync(0xffffffffu, z, 8);
    z += __shfl_xor_sync(0xffffffffu, z, 16);

    if (q == 0) {
        float inv = 1.f / (z + 1e-16f);
#pragma unroll
        for (int i = 0; i < 8; i++) acc[i] *= inv;
        if (do_elu) {
#pragma unroll
            for (int i = 0; i < 8; i++)
                acc[i] = (acc[i] > 0.f) ? acc[i] : (__expf(acc[i]) - 1.f);
        }
        if (is_last) {
            float4 v0 = make_float4(acc[0], acc[1], acc[2], acc[3]);
            float4 v1 = make_float4(acc[4], acc[5], acc[6], acc[7]);
            ((float4*)yext)[(size_t)w * 16 + l8 * 2]     = v0;
            ((float4*)yext)[(size_t)w * 16 + l8 * 2 + 1] = v1;
        } else {
            uint4 pk;
            *reinterpret_cast<__half2*>(&pk.x) = __floats2half2_rn(acc[0], acc[1]);
            *reinterpret_cast<__half2*>(&pk.y) = __floats2half2_rn(acc[2], acc[3]);
            *reinterpret_cast<__half2*>(&pk.z) = __floats2half2_rn(acc[4], acc[5]);
            *reinterpret_cast<__half2*>(&pk.w) = __floats2half2_rn(acc[6], acc[7]);
            *(uint4*)(g_x + (size_t)w * DD + l8 * 8) = pk;
        }
    }
}

// ---------------- launch ----------------
extern "C" void kernel_launch(void* const* d_in, const int* in_sizes, int n_in,
                              void* d_out, int out_size) {
    const float* feat  = (const float*)d_in[0];
    const void*  eidx  = d_in[1];
    const float* W1    = (const float*)d_in[2];
    const float* a_s1  = (const float*)d_in[3];
    const float* a_d1  = (const float*)d_in[4];
    const float* W2    = (const float*)d_in[5];
    const float* a_s2  = (const float*)d_in[6];
    const float* a_d2  = (const float*)d_in[7];
    float* out = (float*)d_out;

    int E = in_sizes[1] / 2;

    static int init_done = 0;
    static cudaStream_t s_side;
    static cudaEvent_t ev_fork, ev_join;
    if (!init_done) {
        cudaStreamCreateWithFlags(&s_side, cudaStreamNonBlocking);
        cudaEventCreateWithFlags(&ev_fork, cudaEventDisableTiming);
        cudaEventCreateWithFlags(&ev_join, cudaEventDisableTiming);
        init_done = 1;
    }

    const int gemm_grid = (NN + BR - 1) / BR;
    const int agg_grid  = (NN * 32 + 255) / 256;
    const int e8_grid   = (E / 8 + 255) / 256;

    // init0 (zero cnt + dtype flag) on main, then fork CSR chain to side.
    k_init0<<<(NN + 255) / 256, 256>>>((const int*)eidx);
    cudaEventRecord(ev_fork, 0);
    cudaStreamWaitEvent(s_side, ev_fork, 0);

    // side stream: CSR build (independent of cvt/gemm)
    k_hist<<<e8_grid, 256, 0, s_side>>>(eidx, E);
    k_scanA<<<NB, 256, 0, s_side>>>();
    k_scanC<<<NB, 256, 0, s_side>>>(E);
    k_scatter<<<e8_grid, 256, 0, s_side>>>(eidx, E);
    cudaEventRecord(ev_join, s_side);

    // main stream: cvt + gemm head 0 (overlaps with CSR build)
    k_cvt<<<(NN * DD + 255) / 256, 256>>>(feat, W1, W2);
    k_gemm<<<gemm_grid, 256>>>(0, a_s1, a_d1);

    // join: agg needs both CSR (side) and gemm0 (main)
    cudaStreamWaitEvent(0, ev_join, 0);
    k_agg<<<agg_grid, 256>>>(out, 0, 0);

    for (int layer = 0; layer < 2; layer++) {
        const float* as = layer ? a_s2 : a_s1;
        const float* ad = layer ? a_d2 : a_d1;
        for (int head = (layer == 0 ? 1 : 0); head < 4; head++) {
            int g = layer * 4 + head;
            int last = (layer == 1 && head == 3);
            int eol  = (head == 3);
            k_gemm<<<gemm_grid, 256>>>(g, as + head * DD, ad + head * DD);
            k_agg<<<agg_grid, 256>>>(out, last, eol);
        }
    }
}

// round 17
// speedup vs baseline: 1.8845x; 1.1047x over previous
#include <cuda_runtime.h>
#include <cuda_fp16.h>
#include <stdint.h>

#define NN 50000
#define EE 800000
#define DD 64
#define BR 128   // rows per GEMM block (8 warps x 16 rows)
#define NB ((NN + 255) / 256)   // 196 scan blocks

// ---------------- device scratch (static, no allocation) ----------------
__device__ int   g_flag;
__device__ int   g_cnt[NN];
__device__ int   g_rowptr[NN + 1];
__device__ int   g_fill[NN];
__device__ int   g_bsum[NB];
__device__ unsigned short g_srcs16[EE];
__device__ __align__(16) __half g_x[NN * DD];           // layer input (fp16)
__device__ __align__(16) __half g_W[8 * DD * DD];       // W^T (fp16), 8 slots
__device__ __align__(16) __half g_hh[NN * DD];          // per-conv h (fp16)
__device__ float g_ssrc[NN];
__device__ float g_sdst[NN];

// ---------------- init0: zero counters + dtype detect (tiny) ------------
__global__ void k_init0(const int* __restrict__ raw) {
    int i = blockIdx.x * blockDim.x + threadIdx.x;
    if (i < NN) g_cnt[i] = 0;
    if (blockIdx.x == 0) {
        __shared__ int ok;
        if (threadIdx.x == 0) ok = 1;
        __syncthreads();
        for (int j = threadIdx.x; j < 4096; j += blockDim.x)
            if (raw[2 * j + 1] != 0) ok = 0;
        __syncthreads();
        if (threadIdx.x == 0) g_flag = ok;
    }
}

// ---------------- cvt: feat + W -> fp16 (W transposed) -------------------
__global__ void k_cvt(const float* __restrict__ feat,
                      const float* __restrict__ W1,
                      const float* __restrict__ W2) {
    int i = blockIdx.x * blockDim.x + threadIdx.x;
    if (i < NN * DD) g_x[i] = __float2half_rn(feat[i]);
    if (i < 8 * DD * DD) {
        int g = i >> 12;
        int idx = i & 4095;
        int k = idx >> 6, c = idx & 63;
        const float* W = (g < 4) ? W1 : W2;
        g_W[g * DD * DD + c * DD + k] =
            __float2half_rn(W[(g & 3) * DD * DD + k * DD + c]);
    }
}

// ---------------- histogram of dst, 8 edges/thread ----------------------
__global__ void k_hist(const void* __restrict__ raw, int E) {
    int base = (blockIdx.x * blockDim.x + threadIdx.x) * 8;
    if (g_flag) {
        const long long* p = (const long long*)raw + E;
#pragma unroll
        for (int u = 0; u < 8; u++) { int j = base + u; if (j < E) atomicAdd(&g_cnt[(int)p[j]], 1); }
    } else {
        const int* p = (const int*)raw + E;
#pragma unroll
        for (int u = 0; u < 8; u++) { int j = base + u; if (j < E) atomicAdd(&g_cnt[p[j]], 1); }
    }
}

// ---------------- 2-phase parallel scan ----------------
__global__ void k_scanA() {
    __shared__ int sh[256];
    int t = threadIdx.x;
    int i = blockIdx.x * 256 + t;
    int v = (i < NN) ? g_cnt[i] : 0;
    sh[t] = v;
    __syncthreads();
#pragma unroll
    for (int off = 1; off < 256; off <<= 1) {
        int u = (t >= off) ? sh[t - off] : 0;
        __syncthreads();
        sh[t] += u;
        __syncthreads();
    }
    if (i < NN) g_rowptr[i] = sh[t] - v;
    if (t == 255) g_bsum[blockIdx.x] = sh[255];
}

__global__ void k_scanC(int E) {
    __shared__ int wsum[8];
    __shared__ int off;
    int t = threadIdx.x;
    int partial = 0;
    for (int j = t; j < blockIdx.x; j += 256) partial += g_bsum[j];
#pragma unroll
    for (int o = 16; o; o >>= 1) partial += __shfl_xor_sync(0xffffffffu, partial, o);
    if ((t & 31) == 0) wsum[t >> 5] = partial;
    __syncthreads();
    if (t == 0) {
        int s = 0;
#pragma unroll
        for (int i = 0; i < 8; i++) s += wsum[i];
        off = s;
    }
    __syncthreads();
    int i = blockIdx.x * 256 + t;
    if (i < NN) {
        int r = g_rowptr[i] + off;
        g_rowptr[i] = r;
        g_fill[i] = r;
    }
    if (i == 0) g_rowptr[NN] = E;
}

// ---------------- scatter into CSR (src only), 8 edges/thread -----------
__global__ void k_scatter(const void* __restrict__ raw, int E) {
    int base = (blockIdx.x * blockDim.x + threadIdx.x) * 8;
    if (g_flag) {
        const long long* p = (const long long*)raw;
#pragma unroll
        for (int u = 0; u < 8; u++) {
            int j = base + u;
            if (j < E) {
                int s = (int)p[j], d = (int)p[E + j];
                int pos = atomicAdd(&g_fill[d], 1);
                g_srcs16[pos] = (unsigned short)s;
            }
        }
    } else {
        const int* p = (const int*)raw;
#pragma unroll
        for (int u = 0; u < 8; u++) {
            int j = base + u;
            if (j < E) {
                int s = p[j], d = p[E + j];
                int pos = atomicAdd(&g_fill[d], 1);
                g_srcs16[pos] = (unsigned short)s;
            }
        }
    }
}

// ---------------- tensor-core GEMM (fp16 single MMA, static smem) -------
__global__ void __launch_bounds__(256) k_gemm(
        int g, const float* __restrict__ a_s, const float* __restrict__ a_d) {
    __shared__ __align__(16) __half Ah[BR][72];   // 18432 B
    __shared__ __align__(16) __half Bh[DD][72];   //  9216 B
    int t = threadIdx.x;
    int rb = blockIdx.x * BR;

    for (int i = t; i < 512; i += 256) {
        int c = i >> 3, q = i & 7;
        ((uint4*)&Bh[c][0])[q] = ((const uint4*)(g_W + g * DD * DD + c * DD))[q];
    }
    for (int i = t; i < 1024; i += 256) {
        int r = i >> 3, q = i & 7;
        int gr = rb + r; if (gr >= NN) gr = 0;
        ((uint4*)&Ah[r][0])[q] = ((const uint4*)(g_x + (size_t)gr * DD))[q];
    }
    __syncthreads();

    int lane = t & 31, wid = t >> 5;
    int gid = lane >> 2, tig = lane & 3;

    float acc[8][4];
#pragma unroll
    for (int nt = 0; nt < 8; nt++)
#pragma unroll
        for (int q = 0; q < 4; q++) acc[nt][q] = 0.f;

#pragma unroll
    for (int ks = 0; ks < 4; ks++) {
        int k0 = ks * 16 + 2 * tig;
        int r0 = wid * 16 + gid;
        uint32_t a[4];
        a[0] = *(const uint32_t*)&Ah[r0][k0];
        a[1] = *(const uint32_t*)&Ah[r0 + 8][k0];
        a[2] = *(const uint32_t*)&Ah[r0][k0 + 8];
        a[3] = *(const uint32_t*)&Ah[r0 + 8][k0 + 8];
#pragma unroll
        for (int nt = 0; nt < 8; nt++) {
            int n = nt * 8 + gid;
            uint32_t b0 = *(const uint32_t*)&Bh[n][k0];
            uint32_t b1 = *(const uint32_t*)&Bh[n][k0 + 8];
            asm volatile(
                "mma.sync.aligned.m16n8k16.row.col.f32.f16.f16.f32 "
                "{%0,%1,%2,%3}, {%4,%5,%6,%7}, {%8,%9}, {%0,%1,%2,%3};"
                : "+f"(acc[nt][0]), "+f"(acc[nt][1]), "+f"(acc[nt][2]), "+f"(acc[nt][3])
                : "r"(a[0]), "r"(a[1]), "r"(a[2]), "r"(a[3]),
                  "r"(b0), "r"(b1));
        }
    }

    float2 asv[8], adv[8];
#pragma unroll
    for (int nt = 0; nt < 8; nt++) {
        asv[nt] = ((const float2*)a_s)[nt * 4 + tig];
        adv[nt] = ((const float2*)a_d)[nt * 4 + tig];
    }
    int r0 = rb + wid * 16 + gid;
    float ss0 = 0.f, sd0 = 0.f, ss1 = 0.f, sd1 = 0.f;
#pragma unroll
    for (int nt = 0; nt < 8; nt++) {
        ss0 = fmaf(acc[nt][0], asv[nt].x, fmaf(acc[nt][1], asv[nt].y, ss0));
        sd0 = fmaf(acc[nt][0], adv[nt].x, fmaf(acc[nt][1], adv[nt].y, sd0));
        ss1 = fmaf(acc[nt][2], asv[nt].x, fmaf(acc[nt][3], asv[nt].y, ss1));
        sd1 = fmaf(acc[nt][2], adv[nt].x, fmaf(acc[nt][3], adv[nt].y, sd1));
    }
#pragma unroll
    for (int o = 1; o <= 2; o <<= 1) {
        ss0 += __shfl_xor_sync(0xffffffffu, ss0, o);
        sd0 += __shfl_xor_sync(0xffffffffu, sd0, o);
        ss1 += __shfl_xor_sync(0xffffffffu, ss1, o);
        sd1 += __shfl_xor_sync(0xffffffffu, sd1, o);
    }
    bool ok0 = (r0 < NN), ok1 = (r0 + 8 < NN);
#pragma unroll
    for (int nt = 0; nt < 8; nt++) {
        int col = nt * 8 + 2 * tig;
        if (ok0)
            *(__half2*)(g_hh + (size_t)r0 * DD + col) =
                __floats2half2_rn(acc[nt][0], acc[nt][1]);
        if (ok1)
            *(__half2*)(g_hh + (size_t)(r0 + 8) * DD + col) =
                __floats2half2_rn(acc[nt][2], acc[nt][3]);
    }
    if (tig == 0) {
        if (ok0) { g_ssrc[r0] = ss0; g_sdst[r0] = sd0; }
        if (ok1) { g_ssrc[r0 + 8] = ss1; g_sdst[r0 + 8] = sd1; }
    }
}

// ---------------- fused agg: register-resident scores + gather ----------
// One warp per dst node. Pass A: lane handles edges lane & lane+32 of the
// segment (deg<=64 covers Poisson(16) always; rare fallback recomputes) —
// ALL score loads in flight at once, 1 exp/edge, (p,s) stay in registers.
// Pass B: quarter-warps gather h; (p,s) arrive via shuffle — no memory
// traffic in the loop besides the compulsory coalesced h gather.
__global__ void __launch_bounds__(256) k_agg(float* __restrict__ yext,
                                             int is_last, int do_elu) {
    int w = (blockIdx.x * blockDim.x + threadIdx.x) >> 5;
    int lane = threadIdx.x & 31;
    if (w >= NN) return;
    int start = g_rowptr[w], end = g_rowptr[w + 1];
    int deg = end - start;
    float sd = g_sdst[w];

    int q = lane >> 3, l8 = lane & 7;
    float acc[8];
#pragma unroll
    for (int i = 0; i < 8; i++) acc[i] = 0.f;
    const uint4* h16 = (const uint4*)g_hh;
    float z = 0.f;

    if (deg <= 64) {
        // pass A: up to 64 edges in registers, max MLP
        float p0 = 0.f, p1 = 0.f;
        int s0 = 0, s1 = 0;
        int j = start + lane;
        if (lane < deg) {
            s0 = g_srcs16[j];
            float e = g_ssrc[s0] + sd;
            e = (e > 0.f) ? e : 0.2f * e;
            p0 = __expf(fminf(e, 60.f));
        }
        if (lane + 32 < deg) {
            s1 = g_srcs16[j + 32];
            float e = g_ssrc[s1] + sd;
            e = (e > 0.f) ? e : 0.2f * e;
            p1 = __expf(fminf(e, 60.f));
        }
        z = p0 + p1;
#pragma unroll
        for (int o = 16; o; o >>= 1) z += __shfl_xor_sync(0xffffffffu, z, o);

        // pass B: 4 edges per iteration, scores via shuffle only
        for (int i0 = 0; i0 < deg; i0 += 4) {
            int e = i0 + q;                      // this quarter's edge index
            int srcLane = e & 31;
            float pa = __shfl_sync(0xffffffffu, p0, srcLane);
            float pb = __shfl_sync(0xffffffffu, p1, srcLane);
            int sa = __shfl_sync(0xffffffffu, s0, srcLane);
            int sb = __shfl_sync(0xffffffffu, s1, srcLane);
            float pq = (e < 32) ? pa : pb;
            int   sq = (e < 32) ? sa : sb;
            if (e < deg) {
                uint4 hv = h16[(size_t)sq * 8 + l8];
                float2 f0 = __half22float2(*reinterpret_cast<const __half2*>(&hv.x));
                float2 f1 = __half22float2(*reinterpret_cast<const __half2*>(&hv.y));
                float2 f2 = __half22float2(*reinterpret_cast<const __half2*>(&hv.z));
                float2 f3 = __half22float2(*reinterpret_cast<const __half2*>(&hv.w));
                acc[0] = fmaf(f0.x, pq, acc[0]);
                acc[1] = fmaf(f0.y, pq, acc[1]);
                acc[2] = fmaf(f1.x, pq, acc[2]);
                acc[3] = fmaf(f1.y, pq, acc[3]);
                acc[4] = fmaf(f2.x, pq, acc[4]);
                acc[5] = fmaf(f2.y, pq, acc[5]);
                acc[6] = fmaf(f3.x, pq, acc[6]);
                acc[7] = fmaf(f3.y, pq, acc[7]);
            }
        }
    } else {
        // fallback (deg > 64): statistically never for Poisson(16)
        for (int j0 = start; j0 < end; j0 += 4) {
            float p = 0.f; int s = 0;
            if (lane < 4) {
                int j = j0 + lane;
                if (j < end) {
                    s = g_srcs16[j];
                    float e = g_ssrc[s] + sd;
                    e = (e > 0.f) ? e : 0.2f * e;
                    p = __expf(fminf(e, 60.f));
                }
            }
            float pq = __shfl_sync(0xffffffffu, p, q);
            int   sq = __shfl_sync(0xffffffffu, s, q);
            z += pq;
            if (j0 + q < end) {
                uint4 hv = h16[(size_t)sq * 8 + l8];
                float2 f0 = __half22float2(*reinterpret_cast<const __half2*>(&hv.x));
                float2 f1 = __half22float2(*reinterpret_cast<const __half2*>(&hv.y));
                float2 f2 = __half22float2(*reinterpret_cast<const __half2*>(&hv.z));
                float2 f3 = __half22float2(*reinterpret_cast<const __half2*>(&hv.w));
                acc[0] = fmaf(f0.x, pq, acc[0]);
                acc[1] = fmaf(f0.y, pq, acc[1]);
                acc[2] = fmaf(f1.x, pq, acc[2]);
                acc[3] = fmaf(f1.y, pq, acc[3]);
                acc[4] = fmaf(f2.x, pq, acc[4]);
                acc[5] = fmaf(f2.y, pq, acc[5]);
                acc[6] = fmaf(f3.x, pq, acc[6]);
                acc[7] = fmaf(f3.y, pq, acc[7]);
            }
        }
        z += __shfl_xor_sync(0xffffffffu, z, 8);
        z += __shfl_xor_sync(0xffffffffu, z, 16);
    }

    // reduce acc over quarter-warps
#pragma unroll
    for (int i = 0; i < 8; i++) {
        acc[i] += __shfl_xor_sync(0xffffffffu, acc[i], 8);
        acc[i] += __shfl_xor_sync(0xffffffffu, acc[i], 16);
    }

    if (q == 0) {
        float inv = 1.f / (z + 1e-16f);
#pragma unroll
        for (int i = 0; i < 8; i++) acc[i] *= inv;
        if (do_elu) {
#pragma unroll
            for (int i = 0; i < 8; i++)
                acc[i] = (acc[i] > 0.f) ? acc[i] : (__expf(acc[i]) - 1.f);
        }
        if (is_last) {
            float4 v0 = make_float4(acc[0], acc[1], acc[2], acc[3]);
            float4 v1 = make_float4(acc[4], acc[5], acc[6], acc[7]);
            ((float4*)yext)[(size_t)w * 16 + l8 * 2]     = v0;
            ((float4*)yext)[(size_t)w * 16 + l8 * 2 + 1] = v1;
        } else {
            uint4 pk;
            *reinterpret_cast<__half2*>(&pk.x) = __floats2half2_rn(acc[0], acc[1]);
            *reinterpret_cast<__half2*>(&pk.y) = __floats2half2_rn(acc[2], acc[3]);
            *reinterpret_cast<__half2*>(&pk.z) = __floats2half2_rn(acc[4], acc[5]);
            *reinterpret_cast<__half2*>(&pk.w) = __floats2half2_rn(acc[6], acc[7]);
            *(uint4*)(g_x + (size_t)w * DD + l8 * 8) = pk;
        }
    }
}

// ---------------- launch ----------------
extern "C" void kernel_launch(void* const* d_in, const int* in_sizes, int n_in,
                              void* d_out, int out_size) {
    const float* feat  = (const float*)d_in[0];
    const void*  eidx  = d_in[1];
    const float* W1    = (const float*)d_in[2];
    const float* a_s1  = (const float*)d_in[3];
    const float* a_d1  = (const float*)d_in[4];
    const float* W2    = (const float*)d_in[5];
    const float* a_s2  = (const float*)d_in[6];
    const float* a_d2  = (const float*)d_in[7];
    float* out = (float*)d_out;

    int E = in_sizes[1] / 2;

    static int init_done = 0;
    static cudaStream_t s_side;
    static cudaEvent_t ev_fork, ev_join;
    if (!init_done) {
        cudaStreamCreateWithFlags(&s_side, cudaStreamNonBlocking);
        cudaEventCreateWithFlags(&ev_fork, cudaEventDisableTiming);
        cudaEventCreateWithFlags(&ev_join, cudaEventDisableTiming);
        init_done = 1;
    }

    const int gemm_grid = (NN + BR - 1) / BR;
    const int agg_grid  = (NN * 32 + 255) / 256;
    const int e8_grid   = (E / 8 + 255) / 256;

    // init0 (zero cnt + dtype flag) on main, then fork CSR chain to side.
    k_init0<<<(NN + 255) / 256, 256>>>((const int*)eidx);
    cudaEventRecord(ev_fork, 0);
    cudaStreamWaitEvent(s_side, ev_fork, 0);

    // side stream: CSR build (independent of cvt/gemm)
    k_hist<<<e8_grid, 256, 0, s_side>>>(eidx, E);
    k_scanA<<<NB, 256, 0, s_side>>>();
    k_scanC<<<NB, 256, 0, s_side>>>(E);
    k_scatter<<<e8_grid, 256, 0, s_side>>>(eidx, E);
    cudaEventRecord(ev_join, s_side);

    // main stream: cvt + gemm head 0 (overlaps with CSR build)
    k_cvt<<<(NN * DD + 255) / 256, 256>>>(feat, W1, W2);
    k_gemm<<<gemm_grid, 256>>>(0, a_s1, a_d1);

    // join: agg needs both CSR (side) and gemm0 (main)
    cudaStreamWaitEvent(0, ev_join, 0);
    k_agg<<<agg_grid, 256>>>(out, 0, 0);

    for (int layer = 0; layer < 2; layer++) {
        const float* as = layer ? a_s2 : a_s1;
        const float* ad = layer ? a_d2 : a_d1;
        for (int head = (layer == 0 ? 1 : 0); head < 4; head++) {
            int g = layer * 4 + head;
            int last = (layer == 1 && head == 3);
            int eol  = (head == 3);
            k_gemm<<<gemm_grid, 256>>>(g, as + head * DD, ad + head * DD);
            k_agg<<<agg_grid, 256>>>(out, last, eol);
        }
    }
}